// round 10
// baseline (speedup 1.0000x reference)
#include <cuda_runtime.h>
#include <cuda_fp16.h>
#include <math.h>

#define Bb 64
#define Ss 128
#define DMm 1024
#define Hh 16
#define DKk 64
#define Mm (Bb*Ss)          // 8192
#define FQ_EPS 1e-8f

// ---------------- device scratch (no allocations allowed) ----------------
__device__ unsigned g_keys[8];          // 0..2: max(q/k/v in), 3: max(attn_out), 4..7: max|Wq/Wk/Wv/Wo|
__device__ unsigned g_spraw[Ss];        // p_attn per-key-column max (raw nonneg float bits)
__device__ float g_sq[Ss], g_sk[Ss], g_sv[Ss];   // per-seq-position int8 scales
__device__ float g_q[Bb*Hh*Ss*DKk];
__device__ float g_k[Bb*Hh*Ss*DKk];
__device__ float g_v[Bb*Hh*Ss*DKk];
__device__ signed char g_qq[Bb*Hh*Ss*DKk];
__device__ signed char g_kq[Bb*Hh*Ss*DKk];
__device__ signed char g_vq[Bb*Hh*Ss*DKk];
__device__ float g_p[Bb*Hh*Ss*Ss];      // p_attn (post-softmax)
__device__ float g_attn[Mm*DMm];        // attention output in [B,S,DM] layout
__device__ unsigned char g_xq[Mm*DMm];  // quantized activations (u8), reused per projection
__device__ signed char   g_wq[DMm*DMm]; // quantized weights (s8), reused per projection

// monotone key for float max via unsigned atomicMax (handles negatives)
__device__ __forceinline__ unsigned fkey(float f) {
    unsigned b = __float_as_uint(f);
    return (b & 0x80000000u) ? ~b : (b | 0x80000000u);
}
__device__ __forceinline__ float funkey(unsigned k) {
    unsigned b = (k & 0x80000000u) ? (k & 0x7fffffffu) : ~k;
    return __uint_as_float(b);
}

// fast exp for x <= 0 (softmax): 2^t with degree-5 poly, rel err ~2.4e-6
__device__ __forceinline__ float fast_exp(float x) {
    float t = x * 1.4426950408889634f;
    t = fmaxf(t, -127.0f);
    float n = rintf(t);
    float f = t - n;
    float p = 1.3333558146428443e-3f;
    p = fmaf(p, f, 9.618129107628477e-3f);
    p = fmaf(p, f, 5.550410866482158e-2f);
    p = fmaf(p, f, 2.402265069591007e-1f);
    p = fmaf(p, f, 6.931471805599453e-1f);
    p = fmaf(p, f, 1.0f);
    float r = __int_as_float(((int)n + 127) << 23);
    return p * r;
}

__device__ __forceinline__ float blockReduceMax(float v) {
    __shared__ float sm[32];
    #pragma unroll
    for (int o = 16; o > 0; o >>= 1) v = fmaxf(v, __shfl_xor_sync(0xffffffffu, v, o));
    int lane = threadIdx.x & 31, w = threadIdx.x >> 5;
    if (lane == 0) sm[w] = v;
    __syncthreads();
    int nw = (blockDim.x + 31) >> 5;
    v = (threadIdx.x < nw) ? sm[threadIdx.x] : -INFINITY;
    if (w == 0) {
        #pragma unroll
        for (int o = 16; o > 0; o >>= 1) v = fmaxf(v, __shfl_xor_sync(0xffffffffu, v, o));
    }
    return v;  // valid in thread 0
}

// ---------------- mma / ldmatrix helpers ----------------
__device__ __forceinline__ void ldsm_x4(unsigned &r0, unsigned &r1, unsigned &r2, unsigned &r3,
                                        const void* p) {
    unsigned a = (unsigned)__cvta_generic_to_shared(p);
    asm volatile("ldmatrix.sync.aligned.m8n8.x4.shared.b16 {%0,%1,%2,%3}, [%4];"
                 : "=r"(r0), "=r"(r1), "=r"(r2), "=r"(r3) : "r"(a));
}
__device__ __forceinline__ void ldsm_x4_t(unsigned &r0, unsigned &r1, unsigned &r2, unsigned &r3,
                                          const void* p) {
    unsigned a = (unsigned)__cvta_generic_to_shared(p);
    asm volatile("ldmatrix.sync.aligned.m8n8.x4.trans.shared.b16 {%0,%1,%2,%3}, [%4];"
                 : "=r"(r0), "=r"(r1), "=r"(r2), "=r"(r3) : "r"(a));
}
__device__ __forceinline__ void mma_u8s8(int* c, const unsigned* a, const unsigned* b) {
    asm volatile("mma.sync.aligned.m16n8k32.row.col.s32.u8.s8.s32 "
                 "{%0,%1,%2,%3}, {%4,%5,%6,%7}, {%8,%9}, {%0,%1,%2,%3};"
                 : "+r"(c[0]), "+r"(c[1]), "+r"(c[2]), "+r"(c[3])
                 : "r"(a[0]), "r"(a[1]), "r"(a[2]), "r"(a[3]), "r"(b[0]), "r"(b[1]));
}
__device__ __forceinline__ void mma_s8s8(int* c, const unsigned* a, const unsigned* b) {
    asm volatile("mma.sync.aligned.m16n8k32.row.col.s32.s8.s8.s32 "
                 "{%0,%1,%2,%3}, {%4,%5,%6,%7}, {%8,%9}, {%0,%1,%2,%3};"
                 : "+r"(c[0]), "+r"(c[1]), "+r"(c[2]), "+r"(c[3])
                 : "r"(a[0]), "r"(a[1]), "r"(a[2]), "r"(a[3]), "r"(b[0]), "r"(b[1]));
}
__device__ __forceinline__ void mma_f16(float* c, const unsigned* a, const unsigned* b) {
    asm volatile("mma.sync.aligned.m16n8k16.row.col.f32.f16.f16.f32 "
                 "{%0,%1,%2,%3}, {%4,%5,%6,%7}, {%8,%9}, {%0,%1,%2,%3};"
                 : "+f"(c[0]), "+f"(c[1]), "+f"(c[2]), "+f"(c[3])
                 : "r"(a[0]), "r"(a[1]), "r"(a[2]), "r"(a[3]), "r"(b[0]), "r"(b[1]));
}

// ---------------- kernels ----------------

__global__ void k_init() {
    int t = threadIdx.x;
    if (t < 8) g_keys[t] = 0u;
    if (t < Ss) g_spraw[t] = 0u;
}

// global max (optionally of |x|) over n4 float4's -> g_keys[slot]; x==nullptr means g_attn
__global__ void k_redmax4(const float4* __restrict__ x, int n4, int slot, int useabs) {
    if (x == nullptr) x = (const float4*)g_attn;
    float m = -INFINITY;
    for (int i = blockIdx.x * blockDim.x + threadIdx.x; i < n4; i += gridDim.x * blockDim.x) {
        float4 v = x[i];
        if (useabs) {
            m = fmaxf(m, fmaxf(fmaxf(fabsf(v.x), fabsf(v.y)), fmaxf(fabsf(v.z), fabsf(v.w))));
        } else {
            m = fmaxf(m, fmaxf(fmaxf(v.x, v.y), fmaxf(v.z, v.w)));
        }
    }
    m = blockReduceMax(m);
    if (threadIdx.x == 0) atomicMax(&g_keys[slot], fkey(m));
}

// quantize activations f32 -> u8 into g_xq (x==nullptr means g_attn)
__global__ void k_quantX(const float4* __restrict__ x, int n4, int slot) {
    if (x == nullptr) x = (const float4*)g_attn;
    float s = fmaxf(funkey(g_keys[slot]), FQ_EPS) / 255.0f;
    uchar4* o = (uchar4*)g_xq;
    for (int i = blockIdx.x * blockDim.x + threadIdx.x; i < n4; i += gridDim.x * blockDim.x) {
        float4 v = x[i];
        uchar4 u;
        u.x = (unsigned char)fminf(fmaxf(rintf(v.x / s), 0.f), 255.f);
        u.y = (unsigned char)fminf(fmaxf(rintf(v.y / s), 0.f), 255.f);
        u.z = (unsigned char)fminf(fmaxf(rintf(v.z / s), 0.f), 255.f);
        u.w = (unsigned char)fminf(fmaxf(rintf(v.w / s), 0.f), 255.f);
        o[i] = u;
    }
}

// quantize weights f32 -> s8 into g_wq
__global__ void k_quantW(const float4* __restrict__ w, int n4, int slot) {
    float s = fmaxf(funkey(g_keys[slot]), FQ_EPS) / 127.0f;
    char4* o = (char4*)g_wq;
    for (int i = blockIdx.x * blockDim.x + threadIdx.x; i < n4; i += gridDim.x * blockDim.x) {
        float4 v = w[i];
        char4 u;
        u.x = (signed char)fminf(fmaxf(rintf(v.x / s), -127.f), 127.f);
        u.y = (signed char)fminf(fmaxf(rintf(v.y / s), -127.f), 127.f);
        u.z = (signed char)fminf(fmaxf(rintf(v.z / s), -127.f), 127.f);
        u.w = (signed char)fminf(fmaxf(rintf(v.w / s), -127.f), 127.f);
        o[i] = u;
    }
}

// int8 tensor-core GEMM: C[m,n] = (sum_d Xq[m,d]*Wq[n,d]) * s_b + round(bias[n]/s_b)*s_b
__global__ __launch_bounds__(256, 2) void k_gemm_i8(const float* __restrict__ bias,
                                                    float* __restrict__ outp,
                                                    int slot_in, int slot_w, int mode) {
    __shared__ unsigned char As[128 * 80];
    __shared__ unsigned char Bs[128 * 80];
    int tid = threadIdx.x, lane = tid & 31, w = tid >> 5;
    int wm = w & 3, wn = w >> 2;           // 4 warps in M, 2 in N
    int bm = blockIdx.y * 128, bn = blockIdx.x * 128;
    int r0 = tid >> 2, q4 = tid & 3;

    int acc[2][8][4] = {};

    int arow_off = (lane & 7) + ((lane >> 3) & 1) * 8;
    int akb = (lane >> 4) * 16;
    int bcol_off = (lane & 7) + (lane >> 4) * 8;
    int bkb = ((lane >> 3) & 1) * 16;

    for (int k0 = 0; k0 < DMm; k0 += 64) {
        int4 xa = *(const int4*)&g_xq[(bm + r0) * DMm + k0 + q4 * 16];
        int4 xb = *(const int4*)&g_xq[(bm + r0 + 64) * DMm + k0 + q4 * 16];
        int4 wa = *(const int4*)&g_wq[(bn + r0) * DMm + k0 + q4 * 16];
        int4 wb = *(const int4*)&g_wq[(bn + r0 + 64) * DMm + k0 + q4 * 16];
        __syncthreads();
        *(int4*)&As[r0 * 80 + q4 * 16] = xa;
        *(int4*)&As[(r0 + 64) * 80 + q4 * 16] = xb;
        *(int4*)&Bs[r0 * 80 + q4 * 16] = wa;
        *(int4*)&Bs[(r0 + 64) * 80 + q4 * 16] = wb;
        __syncthreads();
        #pragma unroll
        for (int ks = 0; ks < 2; ks++) {
            unsigned a[2][4];
            #pragma unroll
            for (int mi = 0; mi < 2; mi++) {
                int row = wm * 32 + mi * 16 + arow_off;
                ldsm_x4(a[mi][0], a[mi][1], a[mi][2], a[mi][3], &As[row * 80 + ks * 32 + akb]);
            }
            unsigned b[8][2];
            #pragma unroll
            for (int pr = 0; pr < 4; pr++) {
                int col = wn * 64 + pr * 16 + bcol_off;
                unsigned t0, t1, t2, t3;
                ldsm_x4(t0, t1, t2, t3, &Bs[col * 80 + ks * 32 + bkb]);
                b[pr * 2][0] = t0; b[pr * 2][1] = t1;
                b[pr * 2 + 1][0] = t2; b[pr * 2 + 1][1] = t3;
            }
            #pragma unroll
            for (int mi = 0; mi < 2; mi++)
                #pragma unroll
                for (int ni = 0; ni < 8; ni++)
                    mma_u8s8(acc[mi][ni], a[mi], b[ni]);
        }
    }

    float s_in = fmaxf(funkey(g_keys[slot_in]), FQ_EPS) / 255.0f;
    float s_w  = fmaxf(funkey(g_keys[slot_w]),  FQ_EPS) / 127.0f;
    float s_b = s_in * s_w;
    int gid = lane >> 2, tg = lane & 3;
    #pragma unroll
    for (int mi = 0; mi < 2; mi++) {
        #pragma unroll
        for (int half = 0; half < 2; half++) {
            int m = bm + wm * 32 + mi * 16 + gid + half * 8;
            int b_ = m >> 7, s_ = m & 127;
            #pragma unroll
            for (int ni = 0; ni < 8; ni++) {
                #pragma unroll
                for (int cc = 0; cc < 2; cc++) {
                    int n = bn + wn * 64 + ni * 8 + tg * 2 + cc;
                    float bq = rintf(bias[n] / s_b) * s_b;
                    float v = (float)acc[mi][ni][half * 2 + cc] * s_b + bq;
                    if (mode < 3) {
                        float* out = (mode == 0) ? g_q : (mode == 1) ? g_k : g_v;
                        int h = n >> 6, dk = n & 63;
                        out[((b_ * Hh + h) * Ss + s_) * DKk + dk] = v;
                    } else {
                        outp[m * DMm + n] = v;
                    }
                }
            }
        }
    }
}

// per-seq-position abs-max scale over (B,H,DK) for g_q/g_k/g_v (sel 0/1/2)
__global__ void k_rowscale(int sel) {
    const float* t = (sel == 0) ? g_q : (sel == 1) ? g_k : g_v;
    float* outp    = (sel == 0) ? g_sq : (sel == 1) ? g_sk : g_sv;
    int s = blockIdx.x;
    float m = 0.f;
    for (int u = threadIdx.x; u < Bb * Hh * DKk; u += blockDim.x) {
        int bh = u >> 6, dk = u & 63;
        m = fmaxf(m, fabsf(t[bh * Ss * DKk + s * DKk + dk]));
    }
    m = blockReduceMax(m);
    if (threadIdx.x == 0) outp[s] = fmaxf(m, FQ_EPS) / 127.0f;
}

// quantize q/k/v (fp32 [bh,s,dk]) -> s8 with per-s scales
__global__ void k_quantqkv() {
    int t = blockIdx.y;
    const float4* src = (t == 0) ? (const float4*)g_q : (t == 1) ? (const float4*)g_k : (const float4*)g_v;
    const float* sc   = (t == 0) ? g_sq : (t == 1) ? g_sk : g_sv;
    char4* dst        = (t == 0) ? (char4*)g_qq : (t == 1) ? (char4*)g_kq : (char4*)g_vq;
    int n4 = Bb * Hh * Ss * DKk / 4;
    for (int i = blockIdx.x * blockDim.x + threadIdx.x; i < n4; i += gridDim.x * blockDim.x) {
        int s = (i >> 4) & 127;
        float sv = sc[s];
        float4 v = src[i];
        char4 o;
        o.x = (signed char)fminf(fmaxf(rintf(v.x / sv), -128.f), 127.f);
        o.y = (signed char)fminf(fmaxf(rintf(v.y / sv), -128.f), 127.f);
        o.z = (signed char)fminf(fmaxf(rintf(v.z / sv), -128.f), 127.f);
        o.w = (signed char)fminf(fmaxf(rintf(v.w / sv), -128.f), 127.f);
        dst[i] = o;
    }
}

// fused scores + softmax + column max: one block per (b,h).
// scores = (qq . kq) * sq[i]*sk[j]/8  (exact s32), mask, softmax rows, p -> g_p,
// per-column p max -> g_spraw.
__global__ __launch_bounds__(256) void k_scores_fused(const int* __restrict__ mask) {
    __shared__ signed char Aq[128 * 80];
    __shared__ signed char Bq[128 * 80];
    __shared__ float sqs[128], sks[128];
    __shared__ float srmax[2][128];
    __shared__ float srsum[2][128];
    __shared__ float sinv[128];
    __shared__ unsigned scol[128];
    int bh = blockIdx.x;
    int b_ = bh >> 4;
    int tid = threadIdx.x, lane = tid & 31, w = tid >> 5;
    int wm = w & 3, wn = w >> 2;

    if (tid < 128) {
        sqs[tid] = g_sq[tid];
        sks[tid] = g_sk[tid];
        scol[tid] = 0u;
    }
    const int4* qsrc = (const int4*)(g_qq + bh * Ss * DKk);
    const int4* ksrc = (const int4*)(g_kq + bh * Ss * DKk);
    #pragma unroll
    for (int part = 0; part < 2; part++) {
        int idx = part * 256 + tid;
        int row = idx >> 2, c16 = idx & 3;
        *(int4*)&Aq[row * 80 + c16 * 16] = qsrc[idx];
        *(int4*)&Bq[row * 80 + c16 * 16] = ksrc[idx];
    }
    __syncthreads();

    int acc[2][8][4] = {};
    int arow_off = (lane & 7) + ((lane >> 3) & 1) * 8;
    int akb = (lane >> 4) * 16;
    int bcol_off = (lane & 7) + (lane >> 4) * 8;
    int bkb = ((lane >> 3) & 1) * 16;
    #pragma unroll
    for (int ks = 0; ks < 2; ks++) {
        unsigned a[2][4];
        #pragma unroll
        for (int mi = 0; mi < 2; mi++) {
            int row = wm * 32 + mi * 16 + arow_off;
            ldsm_x4(a[mi][0], a[mi][1], a[mi][2], a[mi][3], &Aq[row * 80 + ks * 32 + akb]);
        }
        unsigned b[8][2];
        #pragma unroll
        for (int pr = 0; pr < 4; pr++) {
            int col = wn * 64 + pr * 16 + bcol_off;
            unsigned t0, t1, t2, t3;
            ldsm_x4(t0, t1, t2, t3, &Bq[col * 80 + ks * 32 + bkb]);
            b[pr * 2][0] = t0; b[pr * 2][1] = t1;
            b[pr * 2 + 1][0] = t2; b[pr * 2 + 1][1] = t3;
        }
        #pragma unroll
        for (int mi = 0; mi < 2; mi++)
            #pragma unroll
            for (int ni = 0; ni < 8; ni++)
                mma_s8s8(acc[mi][ni], a[mi], b[ni]);
    }

    int gid = lane >> 2, tg = lane & 3;
    const int* mrow = mask + b_ * Ss * Ss;
    float rmax[4] = {-INFINITY, -INFINITY, -INFINITY, -INFINITY};
    #pragma unroll
    for (int mi = 0; mi < 2; mi++) {
        #pragma unroll
        for (int rh = 0; rh < 2; rh++) {
            int i = wm * 32 + mi * 16 + gid + rh * 8;
            float sqi = sqs[i] * 0.125f;
            #pragma unroll
            for (int ni = 0; ni < 8; ni++) {
                #pragma unroll
                for (int cc = 0; cc < 2; cc++) {
                    int j = wn * 64 + ni * 8 + tg * 2 + cc;
                    float v = (float)acc[mi][ni][rh * 2 + cc] * (sqi * sks[j]);
                    if (mrow[i * Ss + j] == 0) v = -1e9f;
                    acc[mi][ni][rh * 2 + cc] = __float_as_int(v);
                    rmax[mi * 2 + rh] = fmaxf(rmax[mi * 2 + rh], v);
                }
            }
        }
    }
    #pragma unroll
    for (int r = 0; r < 4; r++) {
        rmax[r] = fmaxf(rmax[r], __shfl_xor_sync(0xffffffffu, rmax[r], 1));
        rmax[r] = fmaxf(rmax[r], __shfl_xor_sync(0xffffffffu, rmax[r], 2));
    }
    if (tg == 0) {
        #pragma unroll
        for (int mi = 0; mi < 2; mi++)
            #pragma unroll
            for (int rh = 0; rh < 2; rh++)
                srmax[wn][wm * 32 + mi * 16 + gid + rh * 8] = rmax[mi * 2 + rh];
    }
    __syncthreads();

    float rsum[4] = {0.f, 0.f, 0.f, 0.f};
    #pragma unroll
    for (int mi = 0; mi < 2; mi++) {
        #pragma unroll
        for (int rh = 0; rh < 2; rh++) {
            int i = wm * 32 + mi * 16 + gid + rh * 8;
            float rm = fmaxf(srmax[0][i], srmax[1][i]);
            #pragma unroll
            for (int ni = 0; ni < 8; ni++) {
                #pragma unroll
                for (int cc = 0; cc < 2; cc++) {
                    float v = __int_as_float(acc[mi][ni][rh * 2 + cc]);
                    float e = fast_exp(v - rm);
                    acc[mi][ni][rh * 2 + cc] = __float_as_int(e);
                    rsum[mi * 2 + rh] += e;
                }
            }
        }
    }
    #pragma unroll
    for (int r = 0; r < 4; r++) {
        rsum[r] += __shfl_xor_sync(0xffffffffu, rsum[r], 1);
        rsum[r] += __shfl_xor_sync(0xffffffffu, rsum[r], 2);
    }
    if (tg == 0) {
        #pragma unroll
        for (int mi = 0; mi < 2; mi++)
            #pragma unroll
            for (int rh = 0; rh < 2; rh++)
                srsum[wn][wm * 32 + mi * 16 + gid + rh * 8] = rsum[mi * 2 + rh];
    }
    __syncthreads();
    if (tid < 128) sinv[tid] = 1.0f / (srsum[0][tid] + srsum[1][tid]);
    __syncthreads();

    float cmax[16];
    #pragma unroll
    for (int c = 0; c < 16; c++) cmax[c] = 0.f;
    float* pout = g_p + bh * Ss * Ss;
    #pragma unroll
    for (int mi = 0; mi < 2; mi++) {
        #pragma unroll
        for (int rh = 0; rh < 2; rh++) {
            int i = wm * 32 + mi * 16 + gid + rh * 8;
            float iv = sinv[i];
            #pragma unroll
            for (int ni = 0; ni < 8; ni++) {
                float p0 = __int_as_float(acc[mi][ni][rh * 2 + 0]) * iv;
                float p1 = __int_as_float(acc[mi][ni][rh * 2 + 1]) * iv;
                cmax[ni * 2 + 0] = fmaxf(cmax[ni * 2 + 0], p0);
                cmax[ni * 2 + 1] = fmaxf(cmax[ni * 2 + 1], p1);
                *(float2*)&pout[i * Ss + wn * 64 + ni * 8 + tg * 2] = make_float2(p0, p1);
            }
        }
    }
    #pragma unroll
    for (int c = 0; c < 16; c++) {
        cmax[c] = fmaxf(cmax[c], __shfl_xor_sync(0xffffffffu, cmax[c], 4));
        cmax[c] = fmaxf(cmax[c], __shfl_xor_sync(0xffffffffu, cmax[c], 8));
        cmax[c] = fmaxf(cmax[c], __shfl_xor_sync(0xffffffffu, cmax[c], 16));
    }
    if (gid == 0) {
        #pragma unroll
        for (int ni = 0; ni < 8; ni++) {
            #pragma unroll
            for (int cc = 0; cc < 2; cc++)
                atomicMax(&scol[wn * 64 + ni * 8 + tg * 2 + cc], __float_as_uint(cmax[ni * 2 + cc]));
        }
    }
    __syncthreads();
    if (tid < 128) atomicMax(&g_spraw[tid], scol[tid]);
}

// attn: x[i,dk] = sum_j pq[i,j] * (sp[j]*sv[j]*vq[j,dk])  via fp16 MMA, B split hi/lo.
// one block per (b,h); M=128 N=64 K=128 (two 64-j halves).
__global__ __launch_bounds__(256) void k_attn_mma() {
    __shared__ half As[128 * 72];
    __shared__ half Bhh[64 * 72];
    __shared__ half Bll[64 * 72];
    __shared__ float ssp[128];   // sp[j]
    __shared__ float scc[128];   // sp[j]*sv[j]
    int bh = blockIdx.x;
    int b_ = bh >> 4, h_ = bh & 15;
    int tid = threadIdx.x, lane = tid & 31, w = tid >> 5;
    int wm = w & 3, wn = w >> 2;

    if (tid < 128) {
        float sp = fmaxf(__uint_as_float(g_spraw[tid]), FQ_EPS) / 127.0f;
        ssp[tid] = sp;
        scc[tid] = sp * g_sv[tid];
    }
    __syncthreads();

    float acc[2][4][4] = {};
    const float* P = g_p + bh * Ss * Ss;
    const char4* V = (const char4*)(g_vq + bh * Ss * DKk);

    for (int kh = 0; kh < 2; kh++) {
        // A: p[i, kh*64 + jq], quantize to pq (exact in fp16)
        #pragma unroll
        for (int t = 0; t < 8; t++) {
            int idx = t * 256 + tid;
            int i = idx >> 4;
            int jq = (idx & 15) * 4;
            int jg = kh * 64 + jq;
            float4 pv = *(const float4*)&P[i * Ss + jg];
            half h0 = __float2half_rn(fminf(fmaxf(rintf(pv.x / ssp[jg + 0]), -128.f), 127.f));
            half h1 = __float2half_rn(fminf(fmaxf(rintf(pv.y / ssp[jg + 1]), -128.f), 127.f));
            half h2 = __float2half_rn(fminf(fmaxf(rintf(pv.z / ssp[jg + 2]), -128.f), 127.f));
            half h3 = __float2half_rn(fminf(fmaxf(rintf(pv.w / ssp[jg + 3]), -128.f), 127.f));
            half2* dst = (half2*)&As[i * 72 + jq];
            dst[0] = __halves2half2(h0, h1);
            dst[1] = __halves2half2(h2, h3);
        }
        // B: vq[kh*64 + j, dk] * scc -> hi/lo fp16
        #pragma unroll
        for (int t = 0; t < 4; t++) {
            int idx = t * 256 + tid;
            int j = idx >> 4;
            int dk4 = (idx & 15) * 4;
            int jg = kh * 64 + j;
            char4 vv = V[jg * 16 + (idx & 15)];
            float c = scc[jg];
            float f0 = c * (float)vv.x, f1 = c * (float)vv.y;
            float f2 = c * (float)vv.z, f3 = c * (float)vv.w;
            half b0 = __float2half_rn(f0), b1 = __float2half_rn(f1);
            half b2 = __float2half_rn(f2), b3 = __float2half_rn(f3);
            half l0 = __float2half_rn(f0 - __half2float(b0));
            half l1 = __float2half_rn(f1 - __half2float(b1));
            half l2 = __float2half_rn(f2 - __half2float(b2));
            half l3 = __float2half_rn(f3 - __half2float(b3));
            half2* dh = (half2*)&Bhh[j * 72 + dk4];
            dh[0] = __halves2half2(b0, b1); dh[1] = __halves2half2(b2, b3);
            half2* dl = (half2*)&Bll[j * 72 + dk4];
            dl[0] = __halves2half2(l0, l1); dl[1] = __halves2half2(l2, l3);
        }
        __syncthreads();

        #pragma unroll
        for (int ks = 0; ks < 4; ks++) {
            unsigned a[2][4];
            #pragma unroll
            for (int mf = 0; mf < 2; mf++) {
                int row = wm * 32 + mf * 16 + (lane & 15);
                ldsm_x4(a[mf][0], a[mf][1], a[mf][2], a[mf][3],
                        &As[row * 72 + ks * 16 + (lane >> 4) * 8]);
            }
            unsigned bh2[4][2], bl2[4][2];
            #pragma unroll
            for (int nh = 0; nh < 2; nh++) {
                int brow = ks * 16 + (lane & 15);
                int bcol = wn * 32 + nh * 16 + (lane >> 4) * 8;
                unsigned t0, t1, t2, t3;
                ldsm_x4_t(t0, t1, t2, t3, &Bhh[brow * 72 + bcol]);
                bh2[nh * 2][0] = t0; bh2[nh * 2][1] = t1;
                bh2[nh * 2 + 1][0] = t2; bh2[nh * 2 + 1][1] = t3;
                ldsm_x4_t(t0, t1, t2, t3, &Bll[brow * 72 + bcol]);
                bl2[nh * 2][0] = t0; bl2[nh * 2][1] = t1;
                bl2[nh * 2 + 1][0] = t2; bl2[nh * 2 + 1][1] = t3;
            }
            #pragma unroll
            for (int mf = 0; mf < 2; mf++) {
                #pragma unroll
                for (int nf = 0; nf < 4; nf++) {
                    mma_f16(acc[mf][nf], a[mf], bh2[nf]);
                    mma_f16(acc[mf][nf], a[mf], bl2[nf]);
                }
            }
        }
        __syncthreads();
    }

    int gid = lane >> 2, tg = lane & 3;
    #pragma unroll
    for (int mf = 0; mf < 2; mf++) {
        #pragma unroll
        for (int nf = 0; nf < 4; nf++) {
            #pragma unroll
            for (int rh = 0; rh < 2; rh++) {
                int i = wm * 32 + mf * 16 + gid + rh * 8;
                int dk = wn * 32 + nf * 8 + tg * 2;
                *(float2*)&g_attn[(b_ * Ss + i) * DMm + h_ * DKk + dk] =
                    make_float2(acc[mf][nf][rh * 2 + 0], acc[mf][nf][rh * 2 + 1]);
            }
        }
    }
}

extern "C" void kernel_launch(void* const* d_in, const int* in_sizes, int n_in,
                              void* d_out, int out_size) {
    const float* query = (const float*)d_in[0];
    const float* key   = (const float*)d_in[1];
    const float* value = (const float*)d_in[2];
    const int*   mask  = (const int*)d_in[3];
    const float* Wq = (const float*)d_in[4];
    const float* bq = (const float*)d_in[5];
    const float* Wk = (const float*)d_in[6];
    const float* bk = (const float*)d_in[7];
    const float* Wv = (const float*)d_in[8];
    const float* bv = (const float*)d_in[9];
    const float* Wo = (const float*)d_in[10];
    const float* bo = (const float*)d_in[11];
    float* out = (float*)d_out;

    const int NX4 = Mm * DMm / 4;
    const int NW4 = DMm * DMm / 4;

    k_init<<<1, 128>>>();

    k_redmax4<<<1024, 256>>>((const float4*)query, NX4, 0, 0);
    k_redmax4<<<1024, 256>>>((const float4*)key,   NX4, 1, 0);
    k_redmax4<<<1024, 256>>>((const float4*)value, NX4, 2, 0);
    k_redmax4<<<512, 256>>>((const float4*)Wq, NW4, 4, 1);
    k_redmax4<<<512, 256>>>((const float4*)Wk, NW4, 5, 1);
    k_redmax4<<<512, 256>>>((const float4*)Wv, NW4, 6, 1);
    k_redmax4<<<512, 256>>>((const float4*)Wo, NW4, 7, 1);

    dim3 gg(DMm / 128, Mm / 128);
    k_quantX<<<2048, 256>>>((const float4*)query, NX4, 0);
    k_quantW<<<1024, 256>>>((const float4*)Wq, NW4, 4);
    k_gemm_i8<<<gg, 256>>>(bq, nullptr, 0, 4, 0);
    k_quantX<<<2048, 256>>>((const float4*)key, NX4, 1);
    k_quantW<<<1024, 256>>>((const float4*)Wk, NW4, 5);
    k_gemm_i8<<<gg, 256>>>(bk, nullptr, 1, 5, 1);
    k_quantX<<<2048, 256>>>((const float4*)value, NX4, 2);
    k_quantW<<<1024, 256>>>((const float4*)Wv, NW4, 6);
    k_gemm_i8<<<gg, 256>>>(bv, nullptr, 2, 6, 2);

    k_rowscale<<<Ss, 256>>>(0);
    k_rowscale<<<Ss, 256>>>(1);
    k_rowscale<<<Ss, 256>>>(2);
    k_quantqkv<<<dim3(1024, 3), 256>>>();

    k_scores_fused<<<Bb * Hh, 256>>>(mask);
    k_attn_mma<<<Bb * Hh, 256>>>();

    k_redmax4<<<1024, 256>>>(nullptr, NX4, 3, 0);
    k_quantX<<<2048, 256>>>(nullptr, NX4, 3);
    k_quantW<<<1024, 256>>>((const float4*)Wo, NW4, 7);
    k_gemm_i8<<<gg, 256>>>(bo, out, 3, 7, 3);
}

// round 11
// speedup vs baseline: 1.1841x; 1.1841x over previous
#include <cuda_runtime.h>
#include <cuda_fp16.h>
#include <math.h>

#define Bb 64
#define Ss 128
#define DMm 1024
#define Hh 16
#define DKk 64
#define Mm (Bb*Ss)          // 8192
#define FQ_EPS 1e-8f

// ---------------- device scratch (no allocations allowed) ----------------
__device__ unsigned g_keys[8];          // 0..2: max(q/k/v in), 3: max(attn_out), 4..7: max|Wq/Wk/Wv/Wo|
__device__ unsigned g_spraw[Ss];        // p_attn per-key-column max (raw nonneg float bits)
__device__ unsigned g_sraw[3][Ss];      // per-seq-position abs-max raw bits for q/k/v
__device__ float g_q[Bb*Hh*Ss*DKk];
__device__ float g_k[Bb*Hh*Ss*DKk];
__device__ float g_v[Bb*Hh*Ss*DKk];
__device__ signed char g_qq[Bb*Hh*Ss*DKk];
__device__ signed char g_kq[Bb*Hh*Ss*DKk];
__device__ signed char g_vq[Bb*Hh*Ss*DKk];
__device__ float g_p[Bb*Hh*Ss*Ss];      // p_attn (post-softmax)
__device__ float g_attn[Mm*DMm];        // attention output in [B,S,DM] layout
__device__ unsigned char g_xq[Mm*DMm];  // quantized activations (u8), reused per projection
__device__ signed char   g_wq[DMm*DMm]; // quantized weights (s8), reused per projection

// monotone key for float max via unsigned atomicMax (handles negatives)
__device__ __forceinline__ unsigned fkey(float f) {
    unsigned b = __float_as_uint(f);
    return (b & 0x80000000u) ? ~b : (b | 0x80000000u);
}
__device__ __forceinline__ float funkey(unsigned k) {
    unsigned b = (k & 0x80000000u) ? (k & 0x7fffffffu) : ~k;
    return __uint_as_float(b);
}

// fast exp for x <= 0 (softmax): 2^t with degree-5 poly, rel err ~2.4e-6
__device__ __forceinline__ float fast_exp(float x) {
    float t = x * 1.4426950408889634f;
    t = fmaxf(t, -127.0f);
    float n = rintf(t);
    float f = t - n;
    float p = 1.3333558146428443e-3f;
    p = fmaf(p, f, 9.618129107628477e-3f);
    p = fmaf(p, f, 5.550410866482158e-2f);
    p = fmaf(p, f, 2.402265069591007e-1f);
    p = fmaf(p, f, 6.931471805599453e-1f);
    p = fmaf(p, f, 1.0f);
    float r = __int_as_float(((int)n + 127) << 23);
    return p * r;
}

__device__ __forceinline__ float blockReduceMax(float v) {
    __shared__ float sm[32];
    #pragma unroll
    for (int o = 16; o > 0; o >>= 1) v = fmaxf(v, __shfl_xor_sync(0xffffffffu, v, o));
    int lane = threadIdx.x & 31, w = threadIdx.x >> 5;
    if (lane == 0) sm[w] = v;
    __syncthreads();
    int nw = (blockDim.x + 31) >> 5;
    v = (threadIdx.x < nw) ? sm[threadIdx.x] : -INFINITY;
    if (w == 0) {
        #pragma unroll
        for (int o = 16; o > 0; o >>= 1) v = fmaxf(v, __shfl_xor_sync(0xffffffffu, v, o));
    }
    return v;  // valid in thread 0
}

// ---------------- mma / ldmatrix / cp.async helpers ----------------
__device__ __forceinline__ void ldsm_x4(unsigned &r0, unsigned &r1, unsigned &r2, unsigned &r3,
                                        const void* p) {
    unsigned a = (unsigned)__cvta_generic_to_shared(p);
    asm volatile("ldmatrix.sync.aligned.m8n8.x4.shared.b16 {%0,%1,%2,%3}, [%4];"
                 : "=r"(r0), "=r"(r1), "=r"(r2), "=r"(r3) : "r"(a));
}
__device__ __forceinline__ void ldsm_x4_t(unsigned &r0, unsigned &r1, unsigned &r2, unsigned &r3,
                                          const void* p) {
    unsigned a = (unsigned)__cvta_generic_to_shared(p);
    asm volatile("ldmatrix.sync.aligned.m8n8.x4.trans.shared.b16 {%0,%1,%2,%3}, [%4];"
                 : "=r"(r0), "=r"(r1), "=r"(r2), "=r"(r3) : "r"(a));
}
__device__ __forceinline__ void mma_u8s8(int* c, const unsigned* a, const unsigned* b) {
    asm volatile("mma.sync.aligned.m16n8k32.row.col.s32.u8.s8.s32 "
                 "{%0,%1,%2,%3}, {%4,%5,%6,%7}, {%8,%9}, {%0,%1,%2,%3};"
                 : "+r"(c[0]), "+r"(c[1]), "+r"(c[2]), "+r"(c[3])
                 : "r"(a[0]), "r"(a[1]), "r"(a[2]), "r"(a[3]), "r"(b[0]), "r"(b[1]));
}
__device__ __forceinline__ void mma_s8s8(int* c, const unsigned* a, const unsigned* b) {
    asm volatile("mma.sync.aligned.m16n8k32.row.col.s32.s8.s8.s32 "
                 "{%0,%1,%2,%3}, {%4,%5,%6,%7}, {%8,%9}, {%0,%1,%2,%3};"
                 : "+r"(c[0]), "+r"(c[1]), "+r"(c[2]), "+r"(c[3])
                 : "r"(a[0]), "r"(a[1]), "r"(a[2]), "r"(a[3]), "r"(b[0]), "r"(b[1]));
}
__device__ __forceinline__ void mma_f16(float* c, const unsigned* a, const unsigned* b) {
    asm volatile("mma.sync.aligned.m16n8k16.row.col.f32.f16.f16.f32 "
                 "{%0,%1,%2,%3}, {%4,%5,%6,%7}, {%8,%9}, {%0,%1,%2,%3};"
                 : "+f"(c[0]), "+f"(c[1]), "+f"(c[2]), "+f"(c[3])
                 : "r"(a[0]), "r"(a[1]), "r"(a[2]), "r"(a[3]), "r"(b[0]), "r"(b[1]));
}
__device__ __forceinline__ void cp16(void* dst, const void* src) {
    unsigned d = (unsigned)__cvta_generic_to_shared(dst);
    asm volatile("cp.async.cg.shared.global [%0], [%1], 16;" :: "r"(d), "l"(src));
}
__device__ __forceinline__ void cp_commit() { asm volatile("cp.async.commit_group;"); }
__device__ __forceinline__ void cp_wait_all() { asm volatile("cp.async.wait_group 0;"); }

// ---------------- kernels ----------------

__global__ void k_init() {
    int t = threadIdx.x;
    if (t < 8) g_keys[t] = 0u;
    if (t < Ss) g_spraw[t] = 0u;
    if (t < 3 * Ss) ((unsigned*)g_sraw)[t] = 0u;
}

// global max (optionally of |x|) over n4 float4's -> g_keys[slot]
__global__ void k_redmax4(const float4* __restrict__ x, int n4, int slot, int useabs) {
    float m = -INFINITY;
    for (int i = blockIdx.x * blockDim.x + threadIdx.x; i < n4; i += gridDim.x * blockDim.x) {
        float4 v = x[i];
        if (useabs) {
            m = fmaxf(m, fmaxf(fmaxf(fabsf(v.x), fabsf(v.y)), fmaxf(fabsf(v.z), fabsf(v.w))));
        } else {
            m = fmaxf(m, fmaxf(fmaxf(v.x, v.y), fmaxf(v.z, v.w)));
        }
    }
    m = blockReduceMax(m);
    if (threadIdx.x == 0) atomicMax(&g_keys[slot], fkey(m));
}

// quantize activations f32 -> u8 into g_xq (x==nullptr means g_attn)
__global__ void k_quantX(const float4* __restrict__ x, int n4, int slot) {
    if (x == nullptr) x = (const float4*)g_attn;
    float s = fmaxf(funkey(g_keys[slot]), FQ_EPS) / 255.0f;
    uchar4* o = (uchar4*)g_xq;
    for (int i = blockIdx.x * blockDim.x + threadIdx.x; i < n4; i += gridDim.x * blockDim.x) {
        float4 v = x[i];
        uchar4 u;
        u.x = (unsigned char)fminf(fmaxf(rintf(v.x / s), 0.f), 255.f);
        u.y = (unsigned char)fminf(fmaxf(rintf(v.y / s), 0.f), 255.f);
        u.z = (unsigned char)fminf(fmaxf(rintf(v.z / s), 0.f), 255.f);
        u.w = (unsigned char)fminf(fmaxf(rintf(v.w / s), 0.f), 255.f);
        o[i] = u;
    }
}

// quantize weights f32 -> s8 into g_wq
__global__ void k_quantW(const float4* __restrict__ w, int n4, int slot) {
    float s = fmaxf(funkey(g_keys[slot]), FQ_EPS) / 127.0f;
    char4* o = (char4*)g_wq;
    for (int i = blockIdx.x * blockDim.x + threadIdx.x; i < n4; i += gridDim.x * blockDim.x) {
        float4 v = w[i];
        char4 u;
        u.x = (signed char)fminf(fmaxf(rintf(v.x / s), -127.f), 127.f);
        u.y = (signed char)fminf(fmaxf(rintf(v.y / s), -127.f), 127.f);
        u.z = (signed char)fminf(fmaxf(rintf(v.z / s), -127.f), 127.f);
        u.w = (signed char)fminf(fmaxf(rintf(v.w / s), -127.f), 127.f);
        o[i] = u;
    }
}

// int8 tensor-core GEMM with cp.async 2-stage pipeline.
// C[m,n] = (sum_d Xq[m,d]*Wq[n,d]) * s_b + round(bias[n]/s_b)*s_b
// modes 0/1/2: scatter to g_q/g_k/g_v [B,H,S,DK] AND per-s abs-max -> g_sraw[mode]
// mode 3: plain [M,DM] to outp
__global__ __launch_bounds__(256, 2) void k_gemm_i8(const float* __restrict__ bias,
                                                    float* __restrict__ outp,
                                                    int slot_in, int slot_w, int mode) {
    __shared__ unsigned char As[2][128 * 80];
    __shared__ unsigned char Bs[2][128 * 80];
    __shared__ unsigned smax[128];
    int tid = threadIdx.x, lane = tid & 31, w = tid >> 5;
    int wm = w & 3, wn = w >> 2;           // 4 warps in M, 2 in N
    int bm = blockIdx.y * 128, bn = blockIdx.x * 128;
    int r0 = tid >> 2, q4 = (tid & 3) * 16;

    if (tid < 128) smax[tid] = 0u;

    const unsigned char* xb = &g_xq[(bm + r0) * DMm + q4];
    const signed char*   wb = &g_wq[(bn + r0) * DMm + q4];

    // preload chunk 0
    cp16(&As[0][r0 * 80 + q4], xb);
    cp16(&As[0][(r0 + 64) * 80 + q4], xb + 64 * DMm);
    cp16(&Bs[0][r0 * 80 + q4], wb);
    cp16(&Bs[0][(r0 + 64) * 80 + q4], wb + 64 * DMm);
    cp_commit();

    int acc[2][8][4] = {};
    int arow_off = (lane & 7) + ((lane >> 3) & 1) * 8;
    int akb = (lane >> 4) * 16;
    int bcol_off = (lane & 7) + (lane >> 4) * 8;
    int bkb = ((lane >> 3) & 1) * 16;

    for (int it = 0; it < 16; it++) {
        cp_wait_all();
        __syncthreads();
        if (it < 15) {
            int k0 = (it + 1) * 64, nb = (it + 1) & 1;
            cp16(&As[nb][r0 * 80 + q4], xb + k0);
            cp16(&As[nb][(r0 + 64) * 80 + q4], xb + 64 * DMm + k0);
            cp16(&Bs[nb][r0 * 80 + q4], wb + k0);
            cp16(&Bs[nb][(r0 + 64) * 80 + q4], wb + 64 * DMm + k0);
            cp_commit();
        }
        int cb = it & 1;
        #pragma unroll
        for (int ks = 0; ks < 2; ks++) {
            unsigned a[2][4];
            #pragma unroll
            for (int mi = 0; mi < 2; mi++) {
                int row = wm * 32 + mi * 16 + arow_off;
                ldsm_x4(a[mi][0], a[mi][1], a[mi][2], a[mi][3], &As[cb][row * 80 + ks * 32 + akb]);
            }
            unsigned b[8][2];
            #pragma unroll
            for (int pr = 0; pr < 4; pr++) {
                int col = wn * 64 + pr * 16 + bcol_off;
                unsigned t0, t1, t2, t3;
                ldsm_x4(t0, t1, t2, t3, &Bs[cb][col * 80 + ks * 32 + bkb]);
                b[pr * 2][0] = t0; b[pr * 2][1] = t1;
                b[pr * 2 + 1][0] = t2; b[pr * 2 + 1][1] = t3;
            }
            #pragma unroll
            for (int mi = 0; mi < 2; mi++)
                #pragma unroll
                for (int ni = 0; ni < 8; ni++)
                    mma_u8s8(acc[mi][ni], a[mi], b[ni]);
        }
    }

    float s_in = fmaxf(funkey(g_keys[slot_in]), FQ_EPS) / 255.0f;
    float s_w  = fmaxf(funkey(g_keys[slot_w]),  FQ_EPS) / 127.0f;
    float s_b = s_in * s_w;
    int gid = lane >> 2, tg = lane & 3;

    // per-thread n values and quantized bias (16 divisions instead of 64)
    float bqv[16];
    #pragma unroll
    for (int ni = 0; ni < 8; ni++)
        #pragma unroll
        for (int cc = 0; cc < 2; cc++) {
            int n = bn + wn * 64 + ni * 8 + tg * 2 + cc;
            bqv[ni * 2 + cc] = rintf(bias[n] / s_b) * s_b;
        }

    #pragma unroll
    for (int mi = 0; mi < 2; mi++) {
        #pragma unroll
        for (int half = 0; half < 2; half++) {
            int m = bm + wm * 32 + mi * 16 + gid + half * 8;
            int b_ = m >> 7, s_ = m & 127;
            float rowmax = 0.f;
            #pragma unroll
            for (int ni = 0; ni < 8; ni++) {
                #pragma unroll
                for (int cc = 0; cc < 2; cc++) {
                    int n = bn + wn * 64 + ni * 8 + tg * 2 + cc;
                    float v = (float)acc[mi][ni][half * 2 + cc] * s_b + bqv[ni * 2 + cc];
                    if (mode < 3) {
                        float* out = (mode == 0) ? g_q : (mode == 1) ? g_k : g_v;
                        int h = n >> 6, dk = n & 63;
                        out[((b_ * Hh + h) * Ss + s_) * DKk + dk] = v;
                        rowmax = fmaxf(rowmax, fabsf(v));
                    } else {
                        outp[m * DMm + n] = v;
                    }
                }
            }
            if (mode < 3) atomicMax(&smax[s_], __float_as_uint(rowmax));
        }
    }
    if (mode < 3) {
        __syncthreads();
        if (tid < 128) atomicMax(&g_sraw[mode][tid], smax[tid]);
    }
}

// quantize q/k/v (fp32 [bh,s,dk]) -> s8 with per-s scales from g_sraw
__global__ void k_quantqkv() {
    int t = blockIdx.y;
    const float4* src = (t == 0) ? (const float4*)g_q : (t == 1) ? (const float4*)g_k : (const float4*)g_v;
    char4* dst        = (t == 0) ? (char4*)g_qq : (t == 1) ? (char4*)g_kq : (char4*)g_vq;
    int n4 = Bb * Hh * Ss * DKk / 4;
    for (int i = blockIdx.x * blockDim.x + threadIdx.x; i < n4; i += gridDim.x * blockDim.x) {
        int s = (i >> 4) & 127;
        float sv = fmaxf(__uint_as_float(g_sraw[t][s]), FQ_EPS) / 127.0f;
        float4 v = src[i];
        char4 o;
        o.x = (signed char)fminf(fmaxf(rintf(v.x / sv), -128.f), 127.f);
        o.y = (signed char)fminf(fmaxf(rintf(v.y / sv), -128.f), 127.f);
        o.z = (signed char)fminf(fmaxf(rintf(v.z / sv), -128.f), 127.f);
        o.w = (signed char)fminf(fmaxf(rintf(v.w / sv), -128.f), 127.f);
        dst[i] = o;
    }
}

// fused scores + softmax + column max: one block per (b,h).
__global__ __launch_bounds__(256) void k_scores_fused(const int* __restrict__ mask) {
    __shared__ signed char Aq[128 * 80];
    __shared__ signed char Bq[128 * 80];
    __shared__ float sqs[128], sks[128];
    __shared__ float srmax[2][128];
    __shared__ float srsum[2][128];
    __shared__ float sinv[128];
    __shared__ unsigned scol[128];
    int bh = blockIdx.x;
    int b_ = bh >> 4;
    int tid = threadIdx.x, lane = tid & 31, w = tid >> 5;
    int wm = w & 3, wn = w >> 2;

    if (tid < 128) {
        sqs[tid] = fmaxf(__uint_as_float(g_sraw[0][tid]), FQ_EPS) / 127.0f;
        sks[tid] = fmaxf(__uint_as_float(g_sraw[1][tid]), FQ_EPS) / 127.0f;
        scol[tid] = 0u;
    }
    const int4* qsrc = (const int4*)(g_qq + bh * Ss * DKk);
    const int4* ksrc = (const int4*)(g_kq + bh * Ss * DKk);
    #pragma unroll
    for (int part = 0; part < 2; part++) {
        int idx = part * 256 + tid;
        int row = idx >> 2, c16 = idx & 3;
        *(int4*)&Aq[row * 80 + c16 * 16] = qsrc[idx];
        *(int4*)&Bq[row * 80 + c16 * 16] = ksrc[idx];
    }
    __syncthreads();

    int acc[2][8][4] = {};
    int arow_off = (lane & 7) + ((lane >> 3) & 1) * 8;
    int akb = (lane >> 4) * 16;
    int bcol_off = (lane & 7) + (lane >> 4) * 8;
    int bkb = ((lane >> 3) & 1) * 16;
    #pragma unroll
    for (int ks = 0; ks < 2; ks++) {
        unsigned a[2][4];
        #pragma unroll
        for (int mi = 0; mi < 2; mi++) {
            int row = wm * 32 + mi * 16 + arow_off;
            ldsm_x4(a[mi][0], a[mi][1], a[mi][2], a[mi][3], &Aq[row * 80 + ks * 32 + akb]);
        }
        unsigned b[8][2];
        #pragma unroll
        for (int pr = 0; pr < 4; pr++) {
            int col = wn * 64 + pr * 16 + bcol_off;
            unsigned t0, t1, t2, t3;
            ldsm_x4(t0, t1, t2, t3, &Bq[col * 80 + ks * 32 + bkb]);
            b[pr * 2][0] = t0; b[pr * 2][1] = t1;
            b[pr * 2 + 1][0] = t2; b[pr * 2 + 1][1] = t3;
        }
        #pragma unroll
        for (int mi = 0; mi < 2; mi++)
            #pragma unroll
            for (int ni = 0; ni < 8; ni++)
                mma_s8s8(acc[mi][ni], a[mi], b[ni]);
    }

    int gid = lane >> 2, tg = lane & 3;
    const int* mrow = mask + b_ * Ss * Ss;
    float rmax[4] = {-INFINITY, -INFINITY, -INFINITY, -INFINITY};
    #pragma unroll
    for (int mi = 0; mi < 2; mi++) {
        #pragma unroll
        for (int rh = 0; rh < 2; rh++) {
            int i = wm * 32 + mi * 16 + gid + rh * 8;
            float sqi = sqs[i] * 0.125f;
            #pragma unroll
            for (int ni = 0; ni < 8; ni++) {
                #pragma unroll
                for (int cc = 0; cc < 2; cc++) {
                    int j = wn * 64 + ni * 8 + tg * 2 + cc;
                    float v = (float)acc[mi][ni][rh * 2 + cc] * (sqi * sks[j]);
                    if (mrow[i * Ss + j] == 0) v = -1e9f;
                    acc[mi][ni][rh * 2 + cc] = __float_as_int(v);
                    rmax[mi * 2 + rh] = fmaxf(rmax[mi * 2 + rh], v);
                }
            }
        }
    }
    #pragma unroll
    for (int r = 0; r < 4; r++) {
        rmax[r] = fmaxf(rmax[r], __shfl_xor_sync(0xffffffffu, rmax[r], 1));
        rmax[r] = fmaxf(rmax[r], __shfl_xor_sync(0xffffffffu, rmax[r], 2));
    }
    if (tg == 0) {
        #pragma unroll
        for (int mi = 0; mi < 2; mi++)
            #pragma unroll
            for (int rh = 0; rh < 2; rh++)
                srmax[wn][wm * 32 + mi * 16 + gid + rh * 8] = rmax[mi * 2 + rh];
    }
    __syncthreads();

    float rsum[4] = {0.f, 0.f, 0.f, 0.f};
    #pragma unroll
    for (int mi = 0; mi < 2; mi++) {
        #pragma unroll
        for (int rh = 0; rh < 2; rh++) {
            int i = wm * 32 + mi * 16 + gid + rh * 8;
            float rm = fmaxf(srmax[0][i], srmax[1][i]);
            #pragma unroll
            for (int ni = 0; ni < 8; ni++) {
                #pragma unroll
                for (int cc = 0; cc < 2; cc++) {
                    float v = __int_as_float(acc[mi][ni][rh * 2 + cc]);
                    float e = fast_exp(v - rm);
                    acc[mi][ni][rh * 2 + cc] = __float_as_int(e);
                    rsum[mi * 2 + rh] += e;
                }
            }
        }
    }
    #pragma unroll
    for (int r = 0; r < 4; r++) {
        rsum[r] += __shfl_xor_sync(0xffffffffu, rsum[r], 1);
        rsum[r] += __shfl_xor_sync(0xffffffffu, rsum[r], 2);
    }
    if (tg == 0) {
        #pragma unroll
        for (int mi = 0; mi < 2; mi++)
            #pragma unroll
            for (int rh = 0; rh < 2; rh++)
                srsum[wn][wm * 32 + mi * 16 + gid + rh * 8] = rsum[mi * 2 + rh];
    }
    __syncthreads();
    if (tid < 128) sinv[tid] = 1.0f / (srsum[0][tid] + srsum[1][tid]);
    __syncthreads();

    float cmax[16];
    #pragma unroll
    for (int c = 0; c < 16; c++) cmax[c] = 0.f;
    float* pout = g_p + bh * Ss * Ss;
    #pragma unroll
    for (int mi = 0; mi < 2; mi++) {
        #pragma unroll
        for (int rh = 0; rh < 2; rh++) {
            int i = wm * 32 + mi * 16 + gid + rh * 8;
            float iv = sinv[i];
            #pragma unroll
            for (int ni = 0; ni < 8; ni++) {
                float p0 = __int_as_float(acc[mi][ni][rh * 2 + 0]) * iv;
                float p1 = __int_as_float(acc[mi][ni][rh * 2 + 1]) * iv;
                cmax[ni * 2 + 0] = fmaxf(cmax[ni * 2 + 0], p0);
                cmax[ni * 2 + 1] = fmaxf(cmax[ni * 2 + 1], p1);
                *(float2*)&pout[i * Ss + wn * 64 + ni * 8 + tg * 2] = make_float2(p0, p1);
            }
        }
    }
    #pragma unroll
    for (int c = 0; c < 16; c++) {
        cmax[c] = fmaxf(cmax[c], __shfl_xor_sync(0xffffffffu, cmax[c], 4));
        cmax[c] = fmaxf(cmax[c], __shfl_xor_sync(0xffffffffu, cmax[c], 8));
        cmax[c] = fmaxf(cmax[c], __shfl_xor_sync(0xffffffffu, cmax[c], 16));
    }
    if (gid == 0) {
        #pragma unroll
        for (int ni = 0; ni < 8; ni++) {
            #pragma unroll
            for (int cc = 0; cc < 2; cc++)
                atomicMax(&scol[wn * 64 + ni * 8 + tg * 2 + cc], __float_as_uint(cmax[ni * 2 + cc]));
        }
    }
    __syncthreads();
    if (tid < 128) atomicMax(&g_spraw[tid], scol[tid]);
}

// attn: x[i,dk] = sum_j pq[i,j] * (sp[j]*sv[j]*vq[j,dk])  via fp16 MMA, B split hi/lo.
// Also reduces global max(attn_out) -> g_keys[3].
__global__ __launch_bounds__(256) void k_attn_mma() {
    __shared__ half As[128 * 72];
    __shared__ half Bhh[64 * 72];
    __shared__ half Bll[64 * 72];
    __shared__ float ssp[128];   // sp[j]
    __shared__ float scc[128];   // sp[j]*sv[j]
    int bh = blockIdx.x;
    int b_ = bh >> 4, h_ = bh & 15;
    int tid = threadIdx.x, lane = tid & 31, w = tid >> 5;
    int wm = w & 3, wn = w >> 2;

    if (tid < 128) {
        float sp = fmaxf(__uint_as_float(g_spraw[tid]), FQ_EPS) / 127.0f;
        float sv = fmaxf(__uint_as_float(g_sraw[2][tid]), FQ_EPS) / 127.0f;
        ssp[tid] = sp;
        scc[tid] = sp * sv;
    }
    __syncthreads();

    float acc[2][4][4] = {};
    const float* P = g_p + bh * Ss * Ss;
    const char4* V = (const char4*)(g_vq + bh * Ss * DKk);

    for (int kh = 0; kh < 2; kh++) {
        #pragma unroll
        for (int t = 0; t < 8; t++) {
            int idx = t * 256 + tid;
            int i = idx >> 4;
            int jq = (idx & 15) * 4;
            int jg = kh * 64 + jq;
            float4 pv = *(const float4*)&P[i * Ss + jg];
            half h0 = __float2half_rn(fminf(fmaxf(rintf(pv.x / ssp[jg + 0]), -128.f), 127.f));
            half h1 = __float2half_rn(fminf(fmaxf(rintf(pv.y / ssp[jg + 1]), -128.f), 127.f));
            half h2 = __float2half_rn(fminf(fmaxf(rintf(pv.z / ssp[jg + 2]), -128.f), 127.f));
            half h3 = __float2half_rn(fminf(fmaxf(rintf(pv.w / ssp[jg + 3]), -128.f), 127.f));
            half2* dst = (half2*)&As[i * 72 + jq];
            dst[0] = __halves2half2(h0, h1);
            dst[1] = __halves2half2(h2, h3);
        }
        #pragma unroll
        for (int t = 0; t < 4; t++) {
            int idx = t * 256 + tid;
            int j = idx >> 4;
            int dk4 = (idx & 15) * 4;
            int jg = kh * 64 + j;
            char4 vv = V[jg * 16 + (idx & 15)];
            float c = scc[jg];
            float f0 = c * (float)vv.x, f1 = c * (float)vv.y;
            float f2 = c * (float)vv.z, f3 = c * (float)vv.w;
            half b0 = __float2half_rn(f0), b1 = __float2half_rn(f1);
            half b2 = __float2half_rn(f2), b3 = __float2half_rn(f3);
            half l0 = __float2half_rn(f0 - __half2float(b0));
            half l1 = __float2half_rn(f1 - __half2float(b1));
            half l2 = __float2half_rn(f2 - __half2float(b2));
            half l3 = __float2half_rn(f3 - __half2float(b3));
            half2* dh = (half2*)&Bhh[j * 72 + dk4];
            dh[0] = __halves2half2(b0, b1); dh[1] = __halves2half2(b2, b3);
            half2* dl = (half2*)&Bll[j * 72 + dk4];
            dl[0] = __halves2half2(l0, l1); dl[1] = __halves2half2(l2, l3);
        }
        __syncthreads();

        #pragma unroll
        for (int ks = 0; ks < 4; ks++) {
            unsigned a[2][4];
            #pragma unroll
            for (int mf = 0; mf < 2; mf++) {
                int row = wm * 32 + mf * 16 + (lane & 15);
                ldsm_x4(a[mf][0], a[mf][1], a[mf][2], a[mf][3],
                        &As[row * 72 + ks * 16 + (lane >> 4) * 8]);
            }
            unsigned bh2[4][2], bl2[4][2];
            #pragma unroll
            for (int nh = 0; nh < 2; nh++) {
                int brow = ks * 16 + (lane & 15);
                int bcol = wn * 32 + nh * 16 + (lane >> 4) * 8;
                unsigned t0, t1, t2, t3;
                ldsm_x4_t(t0, t1, t2, t3, &Bhh[brow * 72 + bcol]);
                bh2[nh * 2][0] = t0; bh2[nh * 2][1] = t1;
                bh2[nh * 2 + 1][0] = t2; bh2[nh * 2 + 1][1] = t3;
                ldsm_x4_t(t0, t1, t2, t3, &Bll[brow * 72 + bcol]);
                bl2[nh * 2][0] = t0; bl2[nh * 2][1] = t1;
                bl2[nh * 2 + 1][0] = t2; bl2[nh * 2 + 1][1] = t3;
            }
            #pragma unroll
            for (int mf = 0; mf < 2; mf++) {
                #pragma unroll
                for (int nf = 0; nf < 4; nf++) {
                    mma_f16(acc[mf][nf], a[mf], bh2[nf]);
                    mma_f16(acc[mf][nf], a[mf], bl2[nf]);
                }
            }
        }
        __syncthreads();
    }

    int gid = lane >> 2, tg = lane & 3;
    float mx = -INFINITY;
    #pragma unroll
    for (int mf = 0; mf < 2; mf++) {
        #pragma unroll
        for (int nf = 0; nf < 4; nf++) {
            #pragma unroll
            for (int rh = 0; rh < 2; rh++) {
                int i = wm * 32 + mf * 16 + gid + rh * 8;
                int dk = wn * 32 + nf * 8 + tg * 2;
                float v0 = acc[mf][nf][rh * 2 + 0];
                float v1 = acc[mf][nf][rh * 2 + 1];
                mx = fmaxf(mx, fmaxf(v0, v1));
                *(float2*)&g_attn[(b_ * Ss + i) * DMm + h_ * DKk + dk] = make_float2(v0, v1);
            }
        }
    }
    mx = blockReduceMax(mx);
    if (tid == 0) atomicMax(&g_keys[3], fkey(mx));
}

extern "C" void kernel_launch(void* const* d_in, const int* in_sizes, int n_in,
                              void* d_out, int out_size) {
    const float* query = (const float*)d_in[0];
    const float* key   = (const float*)d_in[1];
    const float* value = (const float*)d_in[2];
    const int*   mask  = (const int*)d_in[3];
    const float* Wq = (const float*)d_in[4];
    const float* bq = (const float*)d_in[5];
    const float* Wk = (const float*)d_in[6];
    const float* bk = (const float*)d_in[7];
    const float* Wv = (const float*)d_in[8];
    const float* bv = (const float*)d_in[9];
    const float* Wo = (const float*)d_in[10];
    const float* bo = (const float*)d_in[11];
    float* out = (float*)d_out;

    const int NX4 = Mm * DMm / 4;
    const int NW4 = DMm * DMm / 4;

    k_init<<<1, 512>>>();

    k_redmax4<<<1024, 256>>>((const float4*)query, NX4, 0, 0);
    k_redmax4<<<1024, 256>>>((const float4*)key,   NX4, 1, 0);
    k_redmax4<<<1024, 256>>>((const float4*)value, NX4, 2, 0);
    k_redmax4<<<512, 256>>>((const float4*)Wq, NW4, 4, 1);
    k_redmax4<<<512, 256>>>((const float4*)Wk, NW4, 5, 1);
    k_redmax4<<<512, 256>>>((const float4*)Wv, NW4, 6, 1);
    k_redmax4<<<512, 256>>>((const float4*)Wo, NW4, 7, 1);

    dim3 gg(DMm / 128, Mm / 128);
    k_quantX<<<2048, 256>>>((const float4*)query, NX4, 0);
    k_quantW<<<1024, 256>>>((const float4*)Wq, NW4, 4);
    k_gemm_i8<<<gg, 256>>>(bq, nullptr, 0, 4, 0);
    k_quantX<<<2048, 256>>>((const float4*)key, NX4, 1);
    k_quantW<<<1024, 256>>>((const float4*)Wk, NW4, 5);
    k_gemm_i8<<<gg, 256>>>(bk, nullptr, 1, 5, 1);
    k_quantX<<<2048, 256>>>((const float4*)value, NX4, 2);
    k_quantW<<<1024, 256>>>((const float4*)Wv, NW4, 6);
    k_gemm_i8<<<gg, 256>>>(bv, nullptr, 2, 6, 2);

    k_quantqkv<<<dim3(1024, 3), 256>>>();

    k_scores_fused<<<Bb * Hh, 256>>>(mask);
    k_attn_mma<<<Bb * Hh, 256>>>();

    k_quantX<<<2048, 256>>>(nullptr, NX4, 3);
    k_quantW<<<1024, 256>>>((const float4*)Wo, NW4, 7);
    k_gemm_i8<<<gg, 256>>>(bo, out, 3, 7, 3);
}

// round 13
// speedup vs baseline: 1.2325x; 1.0408x over previous
#include <cuda_runtime.h>
#include <cuda_fp16.h>
#include <math.h>

#define Bb 64
#define Ss 128
#define DMm 1024
#define Hh 16
#define DKk 64
#define Mm (Bb*Ss)          // 8192
#define FQ_EPS 1e-8f
#define GST 10240           // gemm smem bytes per matrix per stage (128*80)

// ---------------- device scratch (no allocations allowed) ----------------
__device__ unsigned g_keys[8];          // 0..2: max(q/k/v in), 3: max(attn_out), 4..7: max|Wq/Wk/Wv/Wo|
__device__ unsigned g_spraw[Ss];        // p_attn per-key-column max (raw nonneg float bits)
__device__ unsigned g_sraw[3][Ss];      // per-seq-position abs-max raw bits for q/k/v
__device__ float g_q[Bb*Hh*Ss*DKk];
__device__ float g_k[Bb*Hh*Ss*DKk];
__device__ float g_v[Bb*Hh*Ss*DKk];
__device__ signed char g_qq[Bb*Hh*Ss*DKk];
__device__ signed char g_kq[Bb*Hh*Ss*DKk];
__device__ signed char g_vq[Bb*Hh*Ss*DKk];
__device__ float g_p[Bb*Hh*Ss*Ss];      // p_attn (post-softmax)
__device__ float g_attn[Mm*DMm];        // attention output in [B,S,DM] layout
__device__ unsigned char g_xq0[Mm*DMm]; // quantized activations (u8) per projection
__device__ unsigned char g_xq1[Mm*DMm];
__device__ unsigned char g_xq2[Mm*DMm];
__device__ signed char   g_wq4[4*DMm*DMm]; // quantized weights (s8), all four

// monotone key for float max via unsigned atomicMax (handles negatives)
__device__ __forceinline__ unsigned fkey(float f) {
    unsigned b = __float_as_uint(f);
    return (b & 0x80000000u) ? ~b : (b | 0x80000000u);
}
__device__ __forceinline__ float funkey(unsigned k) {
    unsigned b = (k & 0x80000000u) ? (k & 0x7fffffffu) : ~k;
    return __uint_as_float(b);
}

// fast exp for x <= 0 (softmax): 2^t with degree-5 poly, rel err ~2.4e-6
__device__ __forceinline__ float fast_exp(float x) {
    float t = x * 1.4426950408889634f;
    t = fmaxf(t, -127.0f);
    float n = rintf(t);
    float f = t - n;
    float p = 1.3333558146428443e-3f;
    p = fmaf(p, f, 9.618129107628477e-3f);
    p = fmaf(p, f, 5.550410866482158e-2f);
    p = fmaf(p, f, 2.402265069591007e-1f);
    p = fmaf(p, f, 6.931471805599453e-1f);
    p = fmaf(p, f, 1.0f);
    float r = __int_as_float(((int)n + 127) << 23);
    return p * r;
}

__device__ __forceinline__ float blockReduceMax(float v) {
    __shared__ float sm[32];
    #pragma unroll
    for (int o = 16; o > 0; o >>= 1) v = fmaxf(v, __shfl_xor_sync(0xffffffffu, v, o));
    int lane = threadIdx.x & 31, w = threadIdx.x >> 5;
    if (lane == 0) sm[w] = v;
    __syncthreads();
    int nw = (blockDim.x + 31) >> 5;
    v = (threadIdx.x < nw) ? sm[threadIdx.x] : -INFINITY;
    if (w == 0) {
        #pragma unroll
        for (int o = 16; o > 0; o >>= 1) v = fmaxf(v, __shfl_xor_sync(0xffffffffu, v, o));
    }
    return v;  // valid in thread 0
}

// ---------------- mma / ldmatrix / cp.async helpers ----------------
__device__ __forceinline__ void ldsm_x4(unsigned &r0, unsigned &r1, unsigned &r2, unsigned &r3,
                                        const void* p) {
    unsigned a = (unsigned)__cvta_generic_to_shared(p);
    asm volatile("ldmatrix.sync.aligned.m8n8.x4.shared.b16 {%0,%1,%2,%3}, [%4];"
                 : "=r"(r0), "=r"(r1), "=r"(r2), "=r"(r3) : "r"(a));
}
__device__ __forceinline__ void ldsm_x4_t(unsigned &r0, unsigned &r1, unsigned &r2, unsigned &r3,
                                          const void* p) {
    unsigned a = (unsigned)__cvta_generic_to_shared(p);
    asm volatile("ldmatrix.sync.aligned.m8n8.x4.trans.shared.b16 {%0,%1,%2,%3}, [%4];"
                 : "=r"(r0), "=r"(r1), "=r"(r2), "=r"(r3) : "r"(a));
}
__device__ __forceinline__ void mma_u8s8(int* c, const unsigned* a, const unsigned* b) {
    asm volatile("mma.sync.aligned.m16n8k32.row.col.s32.u8.s8.s32 "
                 "{%0,%1,%2,%3}, {%4,%5,%6,%7}, {%8,%9}, {%0,%1,%2,%3};"
                 : "+r"(c[0]), "+r"(c[1]), "+r"(c[2]), "+r"(c[3])
                 : "r"(a[0]), "r"(a[1]), "r"(a[2]), "r"(a[3]), "r"(b[0]), "r"(b[1]));
}
__device__ __forceinline__ void mma_s8s8(int* c, const unsigned* a, const unsigned* b) {
    asm volatile("mma.sync.aligned.m16n8k32.row.col.s32.s8.s8.s32 "
                 "{%0,%1,%2,%3}, {%4,%5,%6,%7}, {%8,%9}, {%0,%1,%2,%3};"
                 : "+r"(c[0]), "+r"(c[1]), "+r"(c[2]), "+r"(c[3])
                 : "r"(a[0]), "r"(a[1]), "r"(a[2]), "r"(a[3]), "r"(b[0]), "r"(b[1]));
}
__device__ __forceinline__ void mma_f16(float* c, const unsigned* a, const unsigned* b) {
    asm volatile("mma.sync.aligned.m16n8k16.row.col.f32.f16.f16.f32 "
                 "{%0,%1,%2,%3}, {%4,%5,%6,%7}, {%8,%9}, {%0,%1,%2,%3};"
                 : "+f"(c[0]), "+f"(c[1]), "+f"(c[2]), "+f"(c[3])
                 : "r"(a[0]), "r"(a[1]), "r"(a[2]), "r"(a[3]), "r"(b[0]), "r"(b[1]));
}
__device__ __forceinline__ void cp16(void* dst, const void* src) {
    unsigned d = (unsigned)__cvta_generic_to_shared(dst);
    asm volatile("cp.async.cg.shared.global [%0], [%1], 16;" :: "r"(d), "l"(src));
}
__device__ __forceinline__ void cp_commit() { asm volatile("cp.async.commit_group;"); }

// ---------------- kernels ----------------

__global__ void k_init() {
    int t = threadIdx.x;
    if (t < 8) g_keys[t] = 0u;
    if (t < Ss) g_spraw[t] = 0u;
    if (t < 3 * Ss) ((unsigned*)g_sraw)[t] = 0u;
}

// fused activation redmax: y=0/1/2 -> query/key/value, slots 0..2
__global__ void k_redmaxA(const float4* __restrict__ x0, const float4* __restrict__ x1,
                          const float4* __restrict__ x2, int n4) {
    const float4* x = (blockIdx.y == 0) ? x0 : (blockIdx.y == 1) ? x1 : x2;
    float m = -INFINITY;
    for (int i = blockIdx.x * blockDim.x + threadIdx.x; i < n4; i += gridDim.x * blockDim.x) {
        float4 v = x[i];
        m = fmaxf(m, fmaxf(fmaxf(v.x, v.y), fmaxf(v.z, v.w)));
    }
    m = blockReduceMax(m);
    if (threadIdx.x == 0) atomicMax(&g_keys[blockIdx.y], fkey(m));
}

// fused weight abs-redmax: y=0..3 -> Wq/Wk/Wv/Wo, slots 4..7
__global__ void k_redmaxW(const float4* __restrict__ w0, const float4* __restrict__ w1,
                          const float4* __restrict__ w2, const float4* __restrict__ w3, int n4) {
    const float4* x = (blockIdx.y == 0) ? w0 : (blockIdx.y == 1) ? w1 :
                      (blockIdx.y == 2) ? w2 : w3;
    float m = -INFINITY;
    for (int i = blockIdx.x * blockDim.x + threadIdx.x; i < n4; i += gridDim.x * blockDim.x) {
        float4 v = x[i];
        m = fmaxf(m, fmaxf(fmaxf(fabsf(v.x), fabsf(v.y)), fmaxf(fabsf(v.z), fabsf(v.w))));
    }
    m = blockReduceMax(m);
    if (threadIdx.x == 0) atomicMax(&g_keys[4 + blockIdx.y], fkey(m));
}

// fused activation quant: y=0/1/2 -> query/key/value into g_xq0/1/2
__global__ void k_quantX3(const float4* __restrict__ x0, const float4* __restrict__ x1,
                          const float4* __restrict__ x2, int n4) {
    int t = blockIdx.y;
    const float4* x = (t == 0) ? x0 : (t == 1) ? x1 : x2;
    uchar4* o = (t == 0) ? (uchar4*)g_xq0 : (t == 1) ? (uchar4*)g_xq1 : (uchar4*)g_xq2;
    float s = fmaxf(funkey(g_keys[t]), FQ_EPS) / 255.0f;
    for (int i = blockIdx.x * blockDim.x + threadIdx.x; i < n4; i += gridDim.x * blockDim.x) {
        float4 v = x[i];
        uchar4 u;
        u.x = (unsigned char)fminf(fmaxf(rintf(v.x / s), 0.f), 255.f);
        u.y = (unsigned char)fminf(fmaxf(rintf(v.y / s), 0.f), 255.f);
        u.z = (unsigned char)fminf(fmaxf(rintf(v.z / s), 0.f), 255.f);
        u.w = (unsigned char)fminf(fmaxf(rintf(v.w / s), 0.f), 255.f);
        o[i] = u;
    }
}

// quantize attn output f32 -> u8 into g_xq0 (slot 3)
__global__ void k_quantXattn(int n4) {
    const float4* x = (const float4*)g_attn;
    float s = fmaxf(funkey(g_keys[3]), FQ_EPS) / 255.0f;
    uchar4* o = (uchar4*)g_xq0;
    for (int i = blockIdx.x * blockDim.x + threadIdx.x; i < n4; i += gridDim.x * blockDim.x) {
        float4 v = x[i];
        uchar4 u;
        u.x = (unsigned char)fminf(fmaxf(rintf(v.x / s), 0.f), 255.f);
        u.y = (unsigned char)fminf(fmaxf(rintf(v.y / s), 0.f), 255.f);
        u.z = (unsigned char)fminf(fmaxf(rintf(v.z / s), 0.f), 255.f);
        u.w = (unsigned char)fminf(fmaxf(rintf(v.w / s), 0.f), 255.f);
        o[i] = u;
    }
}

// fused weight quant: y=0..3 -> g_wq4 + y*DMm*DMm
__global__ void k_quantW4(const float4* __restrict__ w0, const float4* __restrict__ w1,
                          const float4* __restrict__ w2, const float4* __restrict__ w3, int n4) {
    int t = blockIdx.y;
    const float4* w = (t == 0) ? w0 : (t == 1) ? w1 : (t == 2) ? w2 : w3;
    float s = fmaxf(funkey(g_keys[4 + t]), FQ_EPS) / 127.0f;
    char4* o = (char4*)(g_wq4 + t * DMm * DMm);
    for (int i = blockIdx.x * blockDim.x + threadIdx.x; i < n4; i += gridDim.x * blockDim.x) {
        float4 v = w[i];
        char4 u;
        u.x = (signed char)fminf(fmaxf(rintf(v.x / s), -127.f), 127.f);
        u.y = (signed char)fminf(fmaxf(rintf(v.y / s), -127.f), 127.f);
        u.z = (signed char)fminf(fmaxf(rintf(v.z / s), -127.f), 127.f);
        u.w = (signed char)fminf(fmaxf(rintf(v.w / s), -127.f), 127.f);
        o[i] = u;
    }
}

// int8 tensor-core GEMM with cp.async 3-stage pipeline (dynamic smem).
// Buffers selected IN-KERNEL via xsel/wsel (device symbols must not cross host boundary).
// C[m,n] = (sum_d Xq[m,d]*Wq[n,d]) * s_b + round(bias[n]/s_b)*s_b
// modes 0/1/2: scatter to g_q/g_k/g_v [B,H,S,DK] AND per-s abs-max -> g_sraw[mode]
// mode 3: plain [M,DM] to outp
__global__ __launch_bounds__(256, 2) void k_gemm_i8(int xsel, int wsel,
                                                    const float* __restrict__ bias,
                                                    float* __restrict__ outp,
                                                    int slot_in, int slot_w, int mode) {
    extern __shared__ unsigned char dyn[];
    unsigned char* As = dyn;               // [3][GST]
    unsigned char* Bs = dyn + 3 * GST;     // [3][GST]
    __shared__ unsigned smax[128];
    const unsigned char* Xq = (xsel == 1) ? g_xq1 : (xsel == 2) ? g_xq2 : g_xq0;
    const signed char*   Wqp = g_wq4 + wsel * DMm * DMm;
    int tid = threadIdx.x, lane = tid & 31, w = tid >> 5;
    int wm = w & 3, wn = w >> 2;           // 4 warps in M, 2 in N
    int bm = blockIdx.y * 128, bn = blockIdx.x * 128;
    int r0 = tid >> 2, q4 = (tid & 3) * 16;

    if (tid < 128) smax[tid] = 0u;

    const unsigned char* xb = &Xq[(bm + r0) * DMm + q4];
    const signed char*   wb = &Wqp[(bn + r0) * DMm + q4];

    // preload chunks 0,1
    #pragma unroll
    for (int pc = 0; pc < 2; pc++) {
        cp16(&As[pc * GST + r0 * 80 + q4], xb + pc * 64);
        cp16(&As[pc * GST + (r0 + 64) * 80 + q4], xb + 64 * DMm + pc * 64);
        cp16(&Bs[pc * GST + r0 * 80 + q4], wb + pc * 64);
        cp16(&Bs[pc * GST + (r0 + 64) * 80 + q4], wb + 64 * DMm + pc * 64);
        cp_commit();
    }

    int acc[2][8][4] = {};
    int arow_off = (lane & 7) + ((lane >> 3) & 1) * 8;
    int akb = (lane >> 4) * 16;
    int bcol_off = (lane & 7) + (lane >> 4) * 8;
    int bkb = ((lane >> 3) & 1) * 16;

    for (int it = 0; it < 16; it++) {
        if (it < 14) asm volatile("cp.async.wait_group 1;");
        else         asm volatile("cp.async.wait_group 0;");
        __syncthreads();
        if (it < 14) {
            int k0 = (it + 2) * 64, nb = (it + 2) % 3;
            cp16(&As[nb * GST + r0 * 80 + q4], xb + k0);
            cp16(&As[nb * GST + (r0 + 64) * 80 + q4], xb + 64 * DMm + k0);
            cp16(&Bs[nb * GST + r0 * 80 + q4], wb + k0);
            cp16(&Bs[nb * GST + (r0 + 64) * 80 + q4], wb + 64 * DMm + k0);
            cp_commit();
        }
        const unsigned char* Ac = &As[(it % 3) * GST];
        const unsigned char* Bc = &Bs[(it % 3) * GST];
        #pragma unroll
        for (int ks = 0; ks < 2; ks++) {
            unsigned a[2][4];
            #pragma unroll
            for (int mi = 0; mi < 2; mi++) {
                int row = wm * 32 + mi * 16 + arow_off;
                ldsm_x4(a[mi][0], a[mi][1], a[mi][2], a[mi][3], &Ac[row * 80 + ks * 32 + akb]);
            }
            unsigned b[8][2];
            #pragma unroll
            for (int pr = 0; pr < 4; pr++) {
                int col = wn * 64 + pr * 16 + bcol_off;
                unsigned t0, t1, t2, t3;
                ldsm_x4(t0, t1, t2, t3, &Bc[col * 80 + ks * 32 + bkb]);
                b[pr * 2][0] = t0; b[pr * 2][1] = t1;
                b[pr * 2 + 1][0] = t2; b[pr * 2 + 1][1] = t3;
            }
            #pragma unroll
            for (int mi = 0; mi < 2; mi++)
                #pragma unroll
                for (int ni = 0; ni < 8; ni++)
                    mma_u8s8(acc[mi][ni], a[mi], b[ni]);
        }
    }

    float s_in = fmaxf(funkey(g_keys[slot_in]), FQ_EPS) / 255.0f;
    float s_w  = fmaxf(funkey(g_keys[slot_w]),  FQ_EPS) / 127.0f;
    float s_b = s_in * s_w;
    int gid = lane >> 2, tg = lane & 3;

    float bqv[16];
    #pragma unroll
    for (int ni = 0; ni < 8; ni++)
        #pragma unroll
        for (int cc = 0; cc < 2; cc++) {
            int n = bn + wn * 64 + ni * 8 + tg * 2 + cc;
            bqv[ni * 2 + cc] = rintf(bias[n] / s_b) * s_b;
        }

    #pragma unroll
    for (int mi = 0; mi < 2; mi++) {
        #pragma unroll
        for (int half = 0; half < 2; half++) {
            int m = bm + wm * 32 + mi * 16 + gid + half * 8;
            int b_ = m >> 7, s_ = m & 127;
            float rowmax = 0.f;
            #pragma unroll
            for (int ni = 0; ni < 8; ni++) {
                #pragma unroll
                for (int cc = 0; cc < 2; cc++) {
                    int n = bn + wn * 64 + ni * 8 + tg * 2 + cc;
                    float v = (float)acc[mi][ni][half * 2 + cc] * s_b + bqv[ni * 2 + cc];
                    if (mode < 3) {
                        float* out = (mode == 0) ? g_q : (mode == 1) ? g_k : g_v;
                        int h = n >> 6, dk = n & 63;
                        out[((b_ * Hh + h) * Ss + s_) * DKk + dk] = v;
                        rowmax = fmaxf(rowmax, fabsf(v));
                    } else {
                        outp[m * DMm + n] = v;
                    }
                }
            }
            if (mode < 3) atomicMax(&smax[s_], __float_as_uint(rowmax));
        }
    }
    if (mode < 3) {
        __syncthreads();
        if (tid < 128) atomicMax(&g_sraw[mode][tid], smax[tid]);
    }
}

// quantize q/k/v (fp32 [bh,s,dk]) -> s8 with per-s scales from g_sraw
__global__ void k_quantqkv() {
    int t = blockIdx.y;
    const float4* src = (t == 0) ? (const float4*)g_q : (t == 1) ? (const float4*)g_k : (const float4*)g_v;
    char4* dst        = (t == 0) ? (char4*)g_qq : (t == 1) ? (char4*)g_kq : (char4*)g_vq;
    int n4 = Bb * Hh * Ss * DKk / 4;
    for (int i = blockIdx.x * blockDim.x + threadIdx.x; i < n4; i += gridDim.x * blockDim.x) {
        int s = (i >> 4) & 127;
        float sv = fmaxf(__uint_as_float(g_sraw[t][s]), FQ_EPS) / 127.0f;
        float4 v = src[i];
        char4 o;
        o.x = (signed char)fminf(fmaxf(rintf(v.x / sv), -128.f), 127.f);
        o.y = (signed char)fminf(fmaxf(rintf(v.y / sv), -128.f), 127.f);
        o.z = (signed char)fminf(fmaxf(rintf(v.z / sv), -128.f), 127.f);
        o.w = (signed char)fminf(fmaxf(rintf(v.w / sv), -128.f), 127.f);
        dst[i] = o;
    }
}

// fused scores + softmax + column max: one block per (b,h).
__global__ __launch_bounds__(256) void k_scores_fused(const int* __restrict__ mask) {
    __shared__ signed char Aq[128 * 80];
    __shared__ signed char Bq[128 * 80];
    __shared__ float sqs[128], sks[128];
    __shared__ float srmax[2][128];
    __shared__ float srsum[2][128];
    __shared__ float sinv[128];
    __shared__ unsigned scol[128];
    int bh = blockIdx.x;
    int b_ = bh >> 4;
    int tid = threadIdx.x, lane = tid & 31, w = tid >> 5;
    int wm = w & 3, wn = w >> 2;

    if (tid < 128) {
        sqs[tid] = fmaxf(__uint_as_float(g_sraw[0][tid]), FQ_EPS) / 127.0f;
        sks[tid] = fmaxf(__uint_as_float(g_sraw[1][tid]), FQ_EPS) / 127.0f;
        scol[tid] = 0u;
    }
    const int4* qsrc = (const int4*)(g_qq + bh * Ss * DKk);
    const int4* ksrc = (const int4*)(g_kq + bh * Ss * DKk);
    #pragma unroll
    for (int part = 0; part < 2; part++) {
        int idx = part * 256 + tid;
        int row = idx >> 2, c16 = idx & 3;
        *(int4*)&Aq[row * 80 + c16 * 16] = qsrc[idx];
        *(int4*)&Bq[row * 80 + c16 * 16] = ksrc[idx];
    }
    __syncthreads();

    int acc[2][8][4] = {};
    int arow_off = (lane & 7) + ((lane >> 3) & 1) * 8;
    int akb = (lane >> 4) * 16;
    int bcol_off = (lane & 7) + (lane >> 4) * 8;
    int bkb = ((lane >> 3) & 1) * 16;
    #pragma unroll
    for (int ks = 0; ks < 2; ks++) {
        unsigned a[2][4];
        #pragma unroll
        for (int mi = 0; mi < 2; mi++) {
            int row = wm * 32 + mi * 16 + arow_off;
            ldsm_x4(a[mi][0], a[mi][1], a[mi][2], a[mi][3], &Aq[row * 80 + ks * 32 + akb]);
        }
        unsigned b[8][2];
        #pragma unroll
        for (int pr = 0; pr < 4; pr++) {
            int col = wn * 64 + pr * 16 + bcol_off;
            unsigned t0, t1, t2, t3;
            ldsm_x4(t0, t1, t2, t3, &Bq[col * 80 + ks * 32 + bkb]);
            b[pr * 2][0] = t0; b[pr * 2][1] = t1;
            b[pr * 2 + 1][0] = t2; b[pr * 2 + 1][1] = t3;
        }
        #pragma unroll
        for (int mi = 0; mi < 2; mi++)
            #pragma unroll
            for (int ni = 0; ni < 8; ni++)
                mma_s8s8(acc[mi][ni], a[mi], b[ni]);
    }

    int gid = lane >> 2, tg = lane & 3;
    const int* mrow = mask + b_ * Ss * Ss;
    float rmax[4] = {-INFINITY, -INFINITY, -INFINITY, -INFINITY};
    #pragma unroll
    for (int mi = 0; mi < 2; mi++) {
        #pragma unroll
        for (int rh = 0; rh < 2; rh++) {
            int i = wm * 32 + mi * 16 + gid + rh * 8;
            float sqi = sqs[i] * 0.125f;
            #pragma unroll
            for (int ni = 0; ni < 8; ni++) {
                #pragma unroll
                for (int cc = 0; cc < 2; cc++) {
                    int j = wn * 64 + ni * 8 + tg * 2 + cc;
                    float v = (float)acc[mi][ni][rh * 2 + cc] * (sqi * sks[j]);
                    if (mrow[i * Ss + j] == 0) v = -1e9f;
                    acc[mi][ni][rh * 2 + cc] = __float_as_int(v);
                    rmax[mi * 2 + rh] = fmaxf(rmax[mi * 2 + rh], v);
                }
            }
        }
    }
    #pragma unroll
    for (int r = 0; r < 4; r++) {
        rmax[r] = fmaxf(rmax[r], __shfl_xor_sync(0xffffffffu, rmax[r], 1));
        rmax[r] = fmaxf(rmax[r], __shfl_xor_sync(0xffffffffu, rmax[r], 2));
    }
    if (tg == 0) {
        #pragma unroll
        for (int mi = 0; mi < 2; mi++)
            #pragma unroll
            for (int rh = 0; rh < 2; rh++)
                srmax[wn][wm * 32 + mi * 16 + gid + rh * 8] = rmax[mi * 2 + rh];
    }
    __syncthreads();

    float rsum[4] = {0.f, 0.f, 0.f, 0.f};
    #pragma unroll
    for (int mi = 0; mi < 2; mi++) {
        #pragma unroll
        for (int rh = 0; rh < 2; rh++) {
            int i = wm * 32 + mi * 16 + gid + rh * 8;
            float rm = fmaxf(srmax[0][i], srmax[1][i]);
            #pragma unroll
            for (int ni = 0; ni < 8; ni++) {
                #pragma unroll
                for (int cc = 0; cc < 2; cc++) {
                    float v = __int_as_float(acc[mi][ni][rh * 2 + cc]);
                    float e = fast_exp(v - rm);
                    acc[mi][ni][rh * 2 + cc] = __float_as_int(e);
                    rsum[mi * 2 + rh] += e;
                }
            }
        }
    }
    #pragma unroll
    for (int r = 0; r < 4; r++) {
        rsum[r] += __shfl_xor_sync(0xffffffffu, rsum[r], 1);
        rsum[r] += __shfl_xor_sync(0xffffffffu, rsum[r], 2);
    }
    if (tg == 0) {
        #pragma unroll
        for (int mi = 0; mi < 2; mi++)
            #pragma unroll
            for (int rh = 0; rh < 2; rh++)
                srsum[wn][wm * 32 + mi * 16 + gid + rh * 8] = rsum[mi * 2 + rh];
    }
    __syncthreads();
    if (tid < 128) sinv[tid] = 1.0f / (srsum[0][tid] + srsum[1][tid]);
    __syncthreads();

    float cmax[16];
    #pragma unroll
    for (int c = 0; c < 16; c++) cmax[c] = 0.f;
    float* pout = g_p + bh * Ss * Ss;
    #pragma unroll
    for (int mi = 0; mi < 2; mi++) {
        #pragma unroll
        for (int rh = 0; rh < 2; rh++) {
            int i = wm * 32 + mi * 16 + gid + rh * 8;
            float iv = sinv[i];
            #pragma unroll
            for (int ni = 0; ni < 8; ni++) {
                float p0 = __int_as_float(acc[mi][ni][rh * 2 + 0]) * iv;
                float p1 = __int_as_float(acc[mi][ni][rh * 2 + 1]) * iv;
                cmax[ni * 2 + 0] = fmaxf(cmax[ni * 2 + 0], p0);
                cmax[ni * 2 + 1] = fmaxf(cmax[ni * 2 + 1], p1);
                *(float2*)&pout[i * Ss + wn * 64 + ni * 8 + tg * 2] = make_float2(p0, p1);
            }
        }
    }
    #pragma unroll
    for (int c = 0; c < 16; c++) {
        cmax[c] = fmaxf(cmax[c], __shfl_xor_sync(0xffffffffu, cmax[c], 4));
        cmax[c] = fmaxf(cmax[c], __shfl_xor_sync(0xffffffffu, cmax[c], 8));
        cmax[c] = fmaxf(cmax[c], __shfl_xor_sync(0xffffffffu, cmax[c], 16));
    }
    if (gid == 0) {
        #pragma unroll
        for (int ni = 0; ni < 8; ni++) {
            #pragma unroll
            for (int cc = 0; cc < 2; cc++)
                atomicMax(&scol[wn * 64 + ni * 8 + tg * 2 + cc], __float_as_uint(cmax[ni * 2 + cc]));
        }
    }
    __syncthreads();
    if (tid < 128) atomicMax(&g_spraw[tid], scol[tid]);
}

// attn: x[i,dk] = sum_j pq[i,j] * (sp[j]*sv[j]*vq[j,dk])  via fp16 MMA, B split hi/lo.
// Also reduces global max(attn_out) -> g_keys[3].
__global__ __launch_bounds__(256) void k_attn_mma() {
    __shared__ half As[128 * 72];
    __shared__ half Bhh[64 * 72];
    __shared__ half Bll[64 * 72];
    __shared__ float ssp[128];
    __shared__ float scc[128];
    int bh = blockIdx.x;
    int b_ = bh >> 4, h_ = bh & 15;
    int tid = threadIdx.x, lane = tid & 31, w = tid >> 5;
    int wm = w & 3, wn = w >> 2;

    if (tid < 128) {
        float sp = fmaxf(__uint_as_float(g_spraw[tid]), FQ_EPS) / 127.0f;
        float sv = fmaxf(__uint_as_float(g_sraw[2][tid]), FQ_EPS) / 127.0f;
        ssp[tid] = sp;
        scc[tid] = sp * sv;
    }
    __syncthreads();

    float acc[2][4][4] = {};
    const float* P = g_p + bh * Ss * Ss;
    const char4* V = (const char4*)(g_vq + bh * Ss * DKk);

    for (int kh = 0; kh < 2; kh++) {
        #pragma unroll
        for (int t = 0; t < 8; t++) {
            int idx = t * 256 + tid;
            int i = idx >> 4;
            int jq = (idx & 15) * 4;
            int jg = kh * 64 + jq;
            float4 pv = *(const float4*)&P[i * Ss + jg];
            half h0 = __float2half_rn(fminf(fmaxf(rintf(pv.x / ssp[jg + 0]), -128.f), 127.f));
            half h1 = __float2half_rn(fminf(fmaxf(rintf(pv.y / ssp[jg + 1]), -128.f), 127.f));
            half h2 = __float2half_rn(fminf(fmaxf(rintf(pv.z / ssp[jg + 2]), -128.f), 127.f));
            half h3 = __float2half_rn(fminf(fmaxf(rintf(pv.w / ssp[jg + 3]), -128.f), 127.f));
            half2* dst = (half2*)&As[i * 72 + jq];
            dst[0] = __halves2half2(h0, h1);
            dst[1] = __halves2half2(h2, h3);
        }
        #pragma unroll
        for (int t = 0; t < 4; t++) {
            int idx = t * 256 + tid;
            int j = idx >> 4;
            int dk4 = (idx & 15) * 4;
            int jg = kh * 64 + j;
            char4 vv = V[jg * 16 + (idx & 15)];
            float c = scc[jg];
            float f0 = c * (float)vv.x, f1 = c * (float)vv.y;
            float f2 = c * (float)vv.z, f3 = c * (float)vv.w;
            half b0 = __float2half_rn(f0), b1 = __float2half_rn(f1);
            half b2 = __float2half_rn(f2), b3 = __float2half_rn(f3);
            half l0 = __float2half_rn(f0 - __half2float(b0));
            half l1 = __float2half_rn(f1 - __half2float(b1));
            half l2 = __float2half_rn(f2 - __half2float(b2));
            half l3 = __float2half_rn(f3 - __half2float(b3));
            half2* dh = (half2*)&Bhh[j * 72 + dk4];
            dh[0] = __halves2half2(b0, b1); dh[1] = __halves2half2(b2, b3);
            half2* dl = (half2*)&Bll[j * 72 + dk4];
            dl[0] = __halves2half2(l0, l1); dl[1] = __halves2half2(l2, l3);
        }
        __syncthreads();

        #pragma unroll
        for (int ks = 0; ks < 4; ks++) {
            unsigned a[2][4];
            #pragma unroll
            for (int mf = 0; mf < 2; mf++) {
                int row = wm * 32 + mf * 16 + (lane & 15);
                ldsm_x4(a[mf][0], a[mf][1], a[mf][2], a[mf][3],
                        &As[row * 72 + ks * 16 + (lane >> 4) * 8]);
            }
            unsigned bh2[4][2], bl2[4][2];
            #pragma unroll
            for (int nh = 0; nh < 2; nh++) {
                int brow = ks * 16 + (lane & 15);
                int bcol = wn * 32 + nh * 16 + (lane >> 4) * 8;
                unsigned t0, t1, t2, t3;
                ldsm_x4_t(t0, t1, t2, t3, &Bhh[brow * 72 + bcol]);
                bh2[nh * 2][0] = t0; bh2[nh * 2][1] = t1;
                bh2[nh * 2 + 1][0] = t2; bh2[nh * 2 + 1][1] = t3;
                ldsm_x4_t(t0, t1, t2, t3, &Bll[brow * 72 + bcol]);
                bl2[nh * 2][0] = t0; bl2[nh * 2][1] = t1;
                bl2[nh * 2 + 1][0] = t2; bl2[nh * 2 + 1][1] = t3;
            }
            #pragma unroll
            for (int mf = 0; mf < 2; mf++) {
                #pragma unroll
                for (int nf = 0; nf < 4; nf++) {
                    mma_f16(acc[mf][nf], a[mf], bh2[nf]);
                    mma_f16(acc[mf][nf], a[mf], bl2[nf]);
                }
            }
        }
        __syncthreads();
    }

    int gid = lane >> 2, tg = lane & 3;
    float mx = -INFINITY;
    #pragma unroll
    for (int mf = 0; mf < 2; mf++) {
        #pragma unroll
        for (int nf = 0; nf < 4; nf++) {
            #pragma unroll
            for (int rh = 0; rh < 2; rh++) {
                int i = wm * 32 + mf * 16 + gid + rh * 8;
                int dk = wn * 32 + nf * 8 + tg * 2;
                float v0 = acc[mf][nf][rh * 2 + 0];
                float v1 = acc[mf][nf][rh * 2 + 1];
                mx = fmaxf(mx, fmaxf(v0, v1));
                *(float2*)&g_attn[(b_ * Ss + i) * DMm + h_ * DKk + dk] = make_float2(v0, v1);
            }
        }
    }
    mx = blockReduceMax(mx);
    if (tid == 0) atomicMax(&g_keys[3], fkey(mx));
}

extern "C" void kernel_launch(void* const* d_in, const int* in_sizes, int n_in,
                              void* d_out, int out_size) {
    const float* query = (const float*)d_in[0];
    const float* key   = (const float*)d_in[1];
    const float* value = (const float*)d_in[2];
    const int*   mask  = (const int*)d_in[3];
    const float* Wq = (const float*)d_in[4];
    const float* bq = (const float*)d_in[5];
    const float* Wk = (const float*)d_in[6];
    const float* bk = (const float*)d_in[7];
    const float* Wv = (const float*)d_in[8];
    const float* bv = (const float*)d_in[9];
    const float* Wo = (const float*)d_in[10];
    const float* bo = (const float*)d_in[11];
    float* out = (float*)d_out;

    const int NX4 = Mm * DMm / 4;
    const int NW4 = DMm * DMm / 4;
    const int GSM = 6 * GST;   // 61440 bytes dynamic smem for gemm

    cudaFuncSetAttribute(k_gemm_i8, cudaFuncAttributeMaxDynamicSharedMemorySize, GSM);

    k_init<<<1, 512>>>();

    k_redmaxA<<<dim3(1024, 3), 256>>>((const float4*)query, (const float4*)key,
                                      (const float4*)value, NX4);
    k_redmaxW<<<dim3(512, 4), 256>>>((const float4*)Wq, (const float4*)Wk,
                                     (const float4*)Wv, (const float4*)Wo, NW4);
    k_quantX3<<<dim3(1024, 3), 256>>>((const float4*)query, (const float4*)key,
                                      (const float4*)value, NX4);
    k_quantW4<<<dim3(512, 4), 256>>>((const float4*)Wq, (const float4*)Wk,
                                     (const float4*)Wv, (const float4*)Wo, NW4);

    dim3 gg(DMm / 128, Mm / 128);
    k_gemm_i8<<<gg, 256, GSM>>>(0, 0, bq, nullptr, 0, 4, 0);
    k_gemm_i8<<<gg, 256, GSM>>>(1, 1, bk, nullptr, 1, 5, 1);
    k_gemm_i8<<<gg, 256, GSM>>>(2, 2, bv, nullptr, 2, 6, 2);

    k_quantqkv<<<dim3(1024, 3), 256>>>();

    k_scores_fused<<<Bb * Hh, 256>>>(mask);
    k_attn_mma<<<Bb * Hh, 256>>>();

    k_quantXattn<<<2048, 256>>>(NX4);
    k_gemm_i8<<<gg, 256, GSM>>>(0, 3, bo, out, 3, 7, 3);
}

// round 14
// speedup vs baseline: 1.2357x; 1.0026x over previous
#include <cuda_runtime.h>
#include <cuda_fp16.h>
#include <math.h>

#define Bb 64
#define Ss 128
#define DMm 1024
#define Hh 16
#define DKk 64
#define Mm (Bb*Ss)          // 8192
#define FQ_EPS 1e-8f
#define GST 10240           // gemm smem bytes per matrix per stage (128*80)

// ---------------- device scratch (no allocations allowed) ----------------
__device__ unsigned g_keys[8];          // 0..2: max(q/k/v in), 3: max(attn_out), 4..7: max|Wq/Wk/Wv/Wo|
__device__ unsigned g_spraw[Ss];        // p_attn per-key-column max (raw nonneg float bits)
__device__ unsigned g_sraw[3][Ss];      // per-seq-position abs-max raw bits for q/k/v
__device__ float g_q[Bb*Hh*Ss*DKk];
__device__ float g_k[Bb*Hh*Ss*DKk];
__device__ float g_v[Bb*Hh*Ss*DKk];
__device__ signed char g_qq[Bb*Hh*Ss*DKk];
__device__ signed char g_kq[Bb*Hh*Ss*DKk];
__device__ signed char g_vq[Bb*Hh*Ss*DKk];
__device__ float g_p[Bb*Hh*Ss*Ss];      // p_attn (post-softmax)
__device__ float g_attn[Mm*DMm];        // attention output in [B,S,DM] layout
__device__ unsigned char g_xq0[Mm*DMm]; // quantized activations (u8) per projection
__device__ unsigned char g_xq1[Mm*DMm];
__device__ unsigned char g_xq2[Mm*DMm];
__device__ signed char   g_wq4[4*DMm*DMm]; // quantized weights (s8), all four

// monotone key for float max via unsigned atomicMax (handles negatives)
__device__ __forceinline__ unsigned fkey(float f) {
    unsigned b = __float_as_uint(f);
    return (b & 0x80000000u) ? ~b : (b | 0x80000000u);
}
__device__ __forceinline__ float funkey(unsigned k) {
    unsigned b = (k & 0x80000000u) ? (k & 0x7fffffffu) : ~k;
    return __uint_as_float(b);
}

// fast exp for x <= 0 (softmax): 2^t with degree-5 poly, rel err ~2.4e-6
__device__ __forceinline__ float fast_exp(float x) {
    float t = x * 1.4426950408889634f;
    t = fmaxf(t, -127.0f);
    float n = rintf(t);
    float f = t - n;
    float p = 1.3333558146428443e-3f;
    p = fmaf(p, f, 9.618129107628477e-3f);
    p = fmaf(p, f, 5.550410866482158e-2f);
    p = fmaf(p, f, 2.402265069591007e-1f);
    p = fmaf(p, f, 6.931471805599453e-1f);
    p = fmaf(p, f, 1.0f);
    float r = __int_as_float(((int)n + 127) << 23);
    return p * r;
}

__device__ __forceinline__ float blockReduceMax(float v) {
    __shared__ float sm[32];
    #pragma unroll
    for (int o = 16; o > 0; o >>= 1) v = fmaxf(v, __shfl_xor_sync(0xffffffffu, v, o));
    int lane = threadIdx.x & 31, w = threadIdx.x >> 5;
    if (lane == 0) sm[w] = v;
    __syncthreads();
    int nw = (blockDim.x + 31) >> 5;
    v = (threadIdx.x < nw) ? sm[threadIdx.x] : -INFINITY;
    if (w == 0) {
        #pragma unroll
        for (int o = 16; o > 0; o >>= 1) v = fmaxf(v, __shfl_xor_sync(0xffffffffu, v, o));
    }
    return v;  // valid in thread 0
}

// ---------------- mma / ldmatrix / cp.async helpers ----------------
__device__ __forceinline__ void ldsm_x4(unsigned &r0, unsigned &r1, unsigned &r2, unsigned &r3,
                                        const void* p) {
    unsigned a = (unsigned)__cvta_generic_to_shared(p);
    asm volatile("ldmatrix.sync.aligned.m8n8.x4.shared.b16 {%0,%1,%2,%3}, [%4];"
                 : "=r"(r0), "=r"(r1), "=r"(r2), "=r"(r3) : "r"(a));
}
__device__ __forceinline__ void ldsm_x4_t(unsigned &r0, unsigned &r1, unsigned &r2, unsigned &r3,
                                          const void* p) {
    unsigned a = (unsigned)__cvta_generic_to_shared(p);
    asm volatile("ldmatrix.sync.aligned.m8n8.x4.trans.shared.b16 {%0,%1,%2,%3}, [%4];"
                 : "=r"(r0), "=r"(r1), "=r"(r2), "=r"(r3) : "r"(a));
}
__device__ __forceinline__ void mma_u8s8(int* c, const unsigned* a, const unsigned* b) {
    asm volatile("mma.sync.aligned.m16n8k32.row.col.s32.u8.s8.s32 "
                 "{%0,%1,%2,%3}, {%4,%5,%6,%7}, {%8,%9}, {%0,%1,%2,%3};"
                 : "+r"(c[0]), "+r"(c[1]), "+r"(c[2]), "+r"(c[3])
                 : "r"(a[0]), "r"(a[1]), "r"(a[2]), "r"(a[3]), "r"(b[0]), "r"(b[1]));
}
__device__ __forceinline__ void mma_s8s8(int* c, const unsigned* a, const unsigned* b) {
    asm volatile("mma.sync.aligned.m16n8k32.row.col.s32.s8.s8.s32 "
                 "{%0,%1,%2,%3}, {%4,%5,%6,%7}, {%8,%9}, {%0,%1,%2,%3};"
                 : "+r"(c[0]), "+r"(c[1]), "+r"(c[2]), "+r"(c[3])
                 : "r"(a[0]), "r"(a[1]), "r"(a[2]), "r"(a[3]), "r"(b[0]), "r"(b[1]));
}
__device__ __forceinline__ void mma_f16(float* c, const unsigned* a, const unsigned* b) {
    asm volatile("mma.sync.aligned.m16n8k16.row.col.f32.f16.f16.f32 "
                 "{%0,%1,%2,%3}, {%4,%5,%6,%7}, {%8,%9}, {%0,%1,%2,%3};"
                 : "+f"(c[0]), "+f"(c[1]), "+f"(c[2]), "+f"(c[3])
                 : "r"(a[0]), "r"(a[1]), "r"(a[2]), "r"(a[3]), "r"(b[0]), "r"(b[1]));
}
__device__ __forceinline__ void cp16(void* dst, const void* src) {
    unsigned d = (unsigned)__cvta_generic_to_shared(dst);
    asm volatile("cp.async.cg.shared.global [%0], [%1], 16;" :: "r"(d), "l"(src));
}
__device__ __forceinline__ void cp_commit() { asm volatile("cp.async.commit_group;"); }

// ---------------- kernels ----------------

__global__ void k_init() {
    int t = threadIdx.x;
    if (t < 8) g_keys[t] = 0u;
    if (t < Ss) g_spraw[t] = 0u;
    if (t < 3 * Ss) ((unsigned*)g_sraw)[t] = 0u;
}

// fused activation redmax: y=0/1/2 -> query/key/value, slots 0..2
__global__ void k_redmaxA(const float4* __restrict__ x0, const float4* __restrict__ x1,
                          const float4* __restrict__ x2, int n4) {
    const float4* x = (blockIdx.y == 0) ? x0 : (blockIdx.y == 1) ? x1 : x2;
    float m = -INFINITY;
    for (int i = blockIdx.x * blockDim.x + threadIdx.x; i < n4; i += gridDim.x * blockDim.x) {
        float4 v = x[i];
        m = fmaxf(m, fmaxf(fmaxf(v.x, v.y), fmaxf(v.z, v.w)));
    }
    m = blockReduceMax(m);
    if (threadIdx.x == 0) atomicMax(&g_keys[blockIdx.y], fkey(m));
}

// fused weight abs-redmax: y=0..3 -> Wq/Wk/Wv/Wo, slots 4..7
__global__ void k_redmaxW(const float4* __restrict__ w0, const float4* __restrict__ w1,
                          const float4* __restrict__ w2, const float4* __restrict__ w3, int n4) {
    const float4* x = (blockIdx.y == 0) ? w0 : (blockIdx.y == 1) ? w1 :
                      (blockIdx.y == 2) ? w2 : w3;
    float m = -INFINITY;
    for (int i = blockIdx.x * blockDim.x + threadIdx.x; i < n4; i += gridDim.x * blockDim.x) {
        float4 v = x[i];
        m = fmaxf(m, fmaxf(fmaxf(fabsf(v.x), fabsf(v.y)), fmaxf(fabsf(v.z), fabsf(v.w))));
    }
    m = blockReduceMax(m);
    if (threadIdx.x == 0) atomicMax(&g_keys[4 + blockIdx.y], fkey(m));
}

// fused activation quant: y=0/1/2 -> query/key/value into g_xq0/1/2
__global__ void k_quantX3(const float4* __restrict__ x0, const float4* __restrict__ x1,
                          const float4* __restrict__ x2, int n4) {
    int t = blockIdx.y;
    const float4* x = (t == 0) ? x0 : (t == 1) ? x1 : x2;
    uchar4* o = (t == 0) ? (uchar4*)g_xq0 : (t == 1) ? (uchar4*)g_xq1 : (uchar4*)g_xq2;
    float s = fmaxf(funkey(g_keys[t]), FQ_EPS) / 255.0f;
    for (int i = blockIdx.x * blockDim.x + threadIdx.x; i < n4; i += gridDim.x * blockDim.x) {
        float4 v = x[i];
        uchar4 u;
        u.x = (unsigned char)fminf(fmaxf(rintf(v.x / s), 0.f), 255.f);
        u.y = (unsigned char)fminf(fmaxf(rintf(v.y / s), 0.f), 255.f);
        u.z = (unsigned char)fminf(fmaxf(rintf(v.z / s), 0.f), 255.f);
        u.w = (unsigned char)fminf(fmaxf(rintf(v.w / s), 0.f), 255.f);
        o[i] = u;
    }
}

// quantize attn output f32 -> u8 into g_xq0 (slot 3)
__global__ void k_quantXattn(int n4) {
    const float4* x = (const float4*)g_attn;
    float s = fmaxf(funkey(g_keys[3]), FQ_EPS) / 255.0f;
    uchar4* o = (uchar4*)g_xq0;
    for (int i = blockIdx.x * blockDim.x + threadIdx.x; i < n4; i += gridDim.x * blockDim.x) {
        float4 v = x[i];
        uchar4 u;
        u.x = (unsigned char)fminf(fmaxf(rintf(v.x / s), 0.f), 255.f);
        u.y = (unsigned char)fminf(fmaxf(rintf(v.y / s), 0.f), 255.f);
        u.z = (unsigned char)fminf(fmaxf(rintf(v.z / s), 0.f), 255.f);
        u.w = (unsigned char)fminf(fmaxf(rintf(v.w / s), 0.f), 255.f);
        o[i] = u;
    }
}

// fused weight quant: y=0..3 -> g_wq4 + y*DMm*DMm
__global__ void k_quantW4(const float4* __restrict__ w0, const float4* __restrict__ w1,
                          const float4* __restrict__ w2, const float4* __restrict__ w3, int n4) {
    int t = blockIdx.y;
    const float4* w = (t == 0) ? w0 : (t == 1) ? w1 : (t == 2) ? w2 : w3;
    float s = fmaxf(funkey(g_keys[4 + t]), FQ_EPS) / 127.0f;
    char4* o = (char4*)(g_wq4 + t * DMm * DMm);
    for (int i = blockIdx.x * blockDim.x + threadIdx.x; i < n4; i += gridDim.x * blockDim.x) {
        float4 v = w[i];
        char4 u;
        u.x = (signed char)fminf(fmaxf(rintf(v.x / s), -127.f), 127.f);
        u.y = (signed char)fminf(fmaxf(rintf(v.y / s), -127.f), 127.f);
        u.z = (signed char)fminf(fmaxf(rintf(v.z / s), -127.f), 127.f);
        u.w = (signed char)fminf(fmaxf(rintf(v.w / s), -127.f), 127.f);
        o[i] = u;
    }
}

// int8 tensor-core GEMM with cp.async 3-stage pipeline (dynamic smem).
// Buffers selected IN-KERNEL via xsel/wsel (device symbols must not cross host boundary).
// C[m,n] = (sum_d Xq[m,d]*Wq[n,d]) * s_b + round(bias[n]/s_b)*s_b
// modes 0/1/2: scatter to g_q/g_k/g_v [B,H,S,DK] AND per-s abs-max -> g_sraw[mode]
// mode 3: plain [M,DM] to outp
__global__ __launch_bounds__(256, 2) void k_gemm_i8(int xsel, int wsel,
                                                    const float* __restrict__ bias,
                                                    float* __restrict__ outp,
                                                    int slot_in, int slot_w, int mode) {
    extern __shared__ unsigned char dyn[];
    unsigned char* As = dyn;               // [3][GST]
    unsigned char* Bs = dyn + 3 * GST;     // [3][GST]
    __shared__ unsigned smax[128];
    const unsigned char* Xq = (xsel == 1) ? g_xq1 : (xsel == 2) ? g_xq2 : g_xq0;
    const signed char*   Wqp = g_wq4 + wsel * DMm * DMm;
    int tid = threadIdx.x, lane = tid & 31, w = tid >> 5;
    int wm = w & 3, wn = w >> 2;           // 4 warps in M, 2 in N
    int bm = blockIdx.y * 128, bn = blockIdx.x * 128;
    int r0 = tid >> 2, q4 = (tid & 3) * 16;

    if (tid < 128) smax[tid] = 0u;

    const unsigned char* xb = &Xq[(bm + r0) * DMm + q4];
    const signed char*   wb = &Wqp[(bn + r0) * DMm + q4];

    // preload chunks 0,1
    #pragma unroll
    for (int pc = 0; pc < 2; pc++) {
        cp16(&As[pc * GST + r0 * 80 + q4], xb + pc * 64);
        cp16(&As[pc * GST + (r0 + 64) * 80 + q4], xb + 64 * DMm + pc * 64);
        cp16(&Bs[pc * GST + r0 * 80 + q4], wb + pc * 64);
        cp16(&Bs[pc * GST + (r0 + 64) * 80 + q4], wb + 64 * DMm + pc * 64);
        cp_commit();
    }

    int acc[2][8][4] = {};
    int arow_off = (lane & 7) + ((lane >> 3) & 1) * 8;
    int akb = (lane >> 4) * 16;
    int bcol_off = (lane & 7) + (lane >> 4) * 8;
    int bkb = ((lane >> 3) & 1) * 16;

    for (int it = 0; it < 16; it++) {
        if (it < 14) asm volatile("cp.async.wait_group 1;");
        else         asm volatile("cp.async.wait_group 0;");
        __syncthreads();
        if (it < 14) {
            int k0 = (it + 2) * 64, nb = (it + 2) % 3;
            cp16(&As[nb * GST + r0 * 80 + q4], xb + k0);
            cp16(&As[nb * GST + (r0 + 64) * 80 + q4], xb + 64 * DMm + k0);
            cp16(&Bs[nb * GST + r0 * 80 + q4], wb + k0);
            cp16(&Bs[nb * GST + (r0 + 64) * 80 + q4], wb + 64 * DMm + k0);
            cp_commit();
        }
        const unsigned char* Ac = &As[(it % 3) * GST];
        const unsigned char* Bc = &Bs[(it % 3) * GST];
        #pragma unroll
        for (int ks = 0; ks < 2; ks++) {
            unsigned a[2][4];
            #pragma unroll
            for (int mi = 0; mi < 2; mi++) {
                int row = wm * 32 + mi * 16 + arow_off;
                ldsm_x4(a[mi][0], a[mi][1], a[mi][2], a[mi][3], &Ac[row * 80 + ks * 32 + akb]);
            }
            unsigned b[8][2];
            #pragma unroll
            for (int pr = 0; pr < 4; pr++) {
                int col = wn * 64 + pr * 16 + bcol_off;
                unsigned t0, t1, t2, t3;
                ldsm_x4(t0, t1, t2, t3, &Bc[col * 80 + ks * 32 + bkb]);
                b[pr * 2][0] = t0; b[pr * 2][1] = t1;
                b[pr * 2 + 1][0] = t2; b[pr * 2 + 1][1] = t3;
            }
            #pragma unroll
            for (int mi = 0; mi < 2; mi++)
                #pragma unroll
                for (int ni = 0; ni < 8; ni++)
                    mma_u8s8(acc[mi][ni], a[mi], b[ni]);
        }
    }

    float s_in = fmaxf(funkey(g_keys[slot_in]), FQ_EPS) / 255.0f;
    float s_w  = fmaxf(funkey(g_keys[slot_w]),  FQ_EPS) / 127.0f;
    float s_b = s_in * s_w;
    int gid = lane >> 2, tg = lane & 3;

    float bqv[16];
    #pragma unroll
    for (int ni = 0; ni < 8; ni++)
        #pragma unroll
        for (int cc = 0; cc < 2; cc++) {
            int n = bn + wn * 64 + ni * 8 + tg * 2 + cc;
            bqv[ni * 2 + cc] = rintf(bias[n] / s_b) * s_b;
        }

    #pragma unroll
    for (int mi = 0; mi < 2; mi++) {
        #pragma unroll
        for (int half = 0; half < 2; half++) {
            int m = bm + wm * 32 + mi * 16 + gid + half * 8;
            int b_ = m >> 7, s_ = m & 127;
            float rowmax = 0.f;
            #pragma unroll
            for (int ni = 0; ni < 8; ni++) {
                #pragma unroll
                for (int cc = 0; cc < 2; cc++) {
                    int n = bn + wn * 64 + ni * 8 + tg * 2 + cc;
                    float v = (float)acc[mi][ni][half * 2 + cc] * s_b + bqv[ni * 2 + cc];
                    if (mode < 3) {
                        float* out = (mode == 0) ? g_q : (mode == 1) ? g_k : g_v;
                        int h = n >> 6, dk = n & 63;
                        out[((b_ * Hh + h) * Ss + s_) * DKk + dk] = v;
                        rowmax = fmaxf(rowmax, fabsf(v));
                    } else {
                        outp[m * DMm + n] = v;
                    }
                }
            }
            if (mode < 3) atomicMax(&smax[s_], __float_as_uint(rowmax));
        }
    }
    if (mode < 3) {
        __syncthreads();
        if (tid < 128) atomicMax(&g_sraw[mode][tid], smax[tid]);
    }
}

// quantize q/k/v (fp32 [bh,s,dk]) -> s8 with per-s scales from g_sraw
__global__ void k_quantqkv() {
    int t = blockIdx.y;
    const float4* src = (t == 0) ? (const float4*)g_q : (t == 1) ? (const float4*)g_k : (const float4*)g_v;
    char4* dst        = (t == 0) ? (char4*)g_qq : (t == 1) ? (char4*)g_kq : (char4*)g_vq;
    int n4 = Bb * Hh * Ss * DKk / 4;
    for (int i = blockIdx.x * blockDim.x + threadIdx.x; i < n4; i += gridDim.x * blockDim.x) {
        int s = (i >> 4) & 127;
        float sv = fmaxf(__uint_as_float(g_sraw[t][s]), FQ_EPS) / 127.0f;
        float4 v = src[i];
        char4 o;
        o.x = (signed char)fminf(fmaxf(rintf(v.x / sv), -128.f), 127.f);
        o.y = (signed char)fminf(fmaxf(rintf(v.y / sv), -128.f), 127.f);
        o.z = (signed char)fminf(fmaxf(rintf(v.z / sv), -128.f), 127.f);
        o.w = (signed char)fminf(fmaxf(rintf(v.w / sv), -128.f), 127.f);
        dst[i] = o;
    }
}

// fused scores + softmax + column max: one block per (b,h).
__global__ __launch_bounds__(256) void k_scores_fused(const int* __restrict__ mask) {
    __shared__ signed char Aq[128 * 80];
    __shared__ signed char Bq[128 * 80];
    __shared__ float sqs[128], sks[128];
    __shared__ float srmax[2][128];
    __shared__ float srsum[2][128];
    __shared__ float sinv[128];
    __shared__ unsigned scol[128];
    int bh = blockIdx.x;
    int b_ = bh >> 4;
    int tid = threadIdx.x, lane = tid & 31, w = tid >> 5;
    int wm = w & 3, wn = w >> 2;

    if (tid < 128) {
        sqs[tid] = fmaxf(__uint_as_float(g_sraw[0][tid]), FQ_EPS) / 127.0f;
        sks[tid] = fmaxf(__uint_as_float(g_sraw[1][tid]), FQ_EPS) / 127.0f;
        scol[tid] = 0u;
    }
    const int4* qsrc = (const int4*)(g_qq + bh * Ss * DKk);
    const int4* ksrc = (const int4*)(g_kq + bh * Ss * DKk);
    #pragma unroll
    for (int part = 0; part < 2; part++) {
        int idx = part * 256 + tid;
        int row = idx >> 2, c16 = idx & 3;
        *(int4*)&Aq[row * 80 + c16 * 16] = qsrc[idx];
        *(int4*)&Bq[row * 80 + c16 * 16] = ksrc[idx];
    }
    __syncthreads();

    int acc[2][8][4] = {};
    int arow_off = (lane & 7) + ((lane >> 3) & 1) * 8;
    int akb = (lane >> 4) * 16;
    int bcol_off = (lane & 7) + (lane >> 4) * 8;
    int bkb = ((lane >> 3) & 1) * 16;
    #pragma unroll
    for (int ks = 0; ks < 2; ks++) {
        unsigned a[2][4];
        #pragma unroll
        for (int mi = 0; mi < 2; mi++) {
            int row = wm * 32 + mi * 16 + arow_off;
            ldsm_x4(a[mi][0], a[mi][1], a[mi][2], a[mi][3], &Aq[row * 80 + ks * 32 + akb]);
        }
        unsigned b[8][2];
        #pragma unroll
        for (int pr = 0; pr < 4; pr++) {
            int col = wn * 64 + pr * 16 + bcol_off;
            unsigned t0, t1, t2, t3;
            ldsm_x4(t0, t1, t2, t3, &Bq[col * 80 + ks * 32 + bkb]);
            b[pr * 2][0] = t0; b[pr * 2][1] = t1;
            b[pr * 2 + 1][0] = t2; b[pr * 2 + 1][1] = t3;
        }
        #pragma unroll
        for (int mi = 0; mi < 2; mi++)
            #pragma unroll
            for (int ni = 0; ni < 8; ni++)
                mma_s8s8(acc[mi][ni], a[mi], b[ni]);
    }

    int gid = lane >> 2, tg = lane & 3;
    const int* mrow = mask + b_ * Ss * Ss;
    float rmax[4] = {-INFINITY, -INFINITY, -INFINITY, -INFINITY};
    #pragma unroll
    for (int mi = 0; mi < 2; mi++) {
        #pragma unroll
        for (int rh = 0; rh < 2; rh++) {
            int i = wm * 32 + mi * 16 + gid + rh * 8;
            float sqi = sqs[i] * 0.125f;
            #pragma unroll
            for (int ni = 0; ni < 8; ni++) {
                #pragma unroll
                for (int cc = 0; cc < 2; cc++) {
                    int j = wn * 64 + ni * 8 + tg * 2 + cc;
                    float v = (float)acc[mi][ni][rh * 2 + cc] * (sqi * sks[j]);
                    if (mrow[i * Ss + j] == 0) v = -1e9f;
                    acc[mi][ni][rh * 2 + cc] = __float_as_int(v);
                    rmax[mi * 2 + rh] = fmaxf(rmax[mi * 2 + rh], v);
                }
            }
        }
    }
    #pragma unroll
    for (int r = 0; r < 4; r++) {
        rmax[r] = fmaxf(rmax[r], __shfl_xor_sync(0xffffffffu, rmax[r], 1));
        rmax[r] = fmaxf(rmax[r], __shfl_xor_sync(0xffffffffu, rmax[r], 2));
    }
    if (tg == 0) {
        #pragma unroll
        for (int mi = 0; mi < 2; mi++)
            #pragma unroll
            for (int rh = 0; rh < 2; rh++)
                srmax[wn][wm * 32 + mi * 16 + gid + rh * 8] = rmax[mi * 2 + rh];
    }
    __syncthreads();

    float rsum[4] = {0.f, 0.f, 0.f, 0.f};
    #pragma unroll
    for (int mi = 0; mi < 2; mi++) {
        #pragma unroll
        for (int rh = 0; rh < 2; rh++) {
            int i = wm * 32 + mi * 16 + gid + rh * 8;
            float rm = fmaxf(srmax[0][i], srmax[1][i]);
            #pragma unroll
            for (int ni = 0; ni < 8; ni++) {
                #pragma unroll
                for (int cc = 0; cc < 2; cc++) {
                    float v = __int_as_float(acc[mi][ni][rh * 2 + cc]);
                    float e = fast_exp(v - rm);
                    acc[mi][ni][rh * 2 + cc] = __float_as_int(e);
                    rsum[mi * 2 + rh] += e;
                }
            }
        }
    }
    #pragma unroll
    for (int r = 0; r < 4; r++) {
        rsum[r] += __shfl_xor_sync(0xffffffffu, rsum[r], 1);
        rsum[r] += __shfl_xor_sync(0xffffffffu, rsum[r], 2);
    }
    if (tg == 0) {
        #pragma unroll
        for (int mi = 0; mi < 2; mi++)
            #pragma unroll
            for (int rh = 0; rh < 2; rh++)
                srsum[wn][wm * 32 + mi * 16 + gid + rh * 8] = rsum[mi * 2 + rh];
    }
    __syncthreads();
    if (tid < 128) sinv[tid] = 1.0f / (srsum[0][tid] + srsum[1][tid]);
    __syncthreads();

    float cmax[16];
    #pragma unroll
    for (int c = 0; c < 16; c++) cmax[c] = 0.f;
    float* pout = g_p + bh * Ss * Ss;
    #pragma unroll
    for (int mi = 0; mi < 2; mi++) {
        #pragma unroll
        for (int rh = 0; rh < 2; rh++) {
            int i = wm * 32 + mi * 16 + gid + rh * 8;
            float iv = sinv[i];
            #pragma unroll
            for (int ni = 0; ni < 8; ni++) {
                float p0 = __int_as_float(acc[mi][ni][rh * 2 + 0]) * iv;
                float p1 = __int_as_float(acc[mi][ni][rh * 2 + 1]) * iv;
                cmax[ni * 2 + 0] = fmaxf(cmax[ni * 2 + 0], p0);
                cmax[ni * 2 + 1] = fmaxf(cmax[ni * 2 + 1], p1);
                *(float2*)&pout[i * Ss + wn * 64 + ni * 8 + tg * 2] = make_float2(p0, p1);
            }
        }
    }
    #pragma unroll
    for (int c = 0; c < 16; c++) {
        cmax[c] = fmaxf(cmax[c], __shfl_xor_sync(0xffffffffu, cmax[c], 4));
        cmax[c] = fmaxf(cmax[c], __shfl_xor_sync(0xffffffffu, cmax[c], 8));
        cmax[c] = fmaxf(cmax[c], __shfl_xor_sync(0xffffffffu, cmax[c], 16));
    }
    if (gid == 0) {
        #pragma unroll
        for (int ni = 0; ni < 8; ni++) {
            #pragma unroll
            for (int cc = 0; cc < 2; cc++)
                atomicMax(&scol[wn * 64 + ni * 8 + tg * 2 + cc], __float_as_uint(cmax[ni * 2 + cc]));
        }
    }
    __syncthreads();
    if (tid < 128) atomicMax(&g_spraw[tid], scol[tid]);
}

// attn: x[i,dk] = sum_j pq[i,j] * (sp[j]*sv[j]*vq[j,dk])  via fp16 MMA, B split hi/lo.
// Also reduces global max(attn_out) -> g_keys[3].
__global__ __launch_bounds__(256) void k_attn_mma() {
    __shared__ half As[128 * 72];
    __shared__ half Bhh[64 * 72];
    __shared__ half Bll[64 * 72];
    __shared__ float ssp[128];
    __shared__ float scc[128];
    int bh = blockIdx.x;
    int b_ = bh >> 4, h_ = bh & 15;
    int tid = threadIdx.x, lane = tid & 31, w = tid >> 5;
    int wm = w & 3, wn = w >> 2;

    if (tid < 128) {
        float sp = fmaxf(__uint_as_float(g_spraw[tid]), FQ_EPS) / 127.0f;
        float sv = fmaxf(__uint_as_float(g_sraw[2][tid]), FQ_EPS) / 127.0f;
        ssp[tid] = sp;
        scc[tid] = sp * sv;
    }
    __syncthreads();

    float acc[2][4][4] = {};
    const float* P = g_p + bh * Ss * Ss;
    const char4* V = (const char4*)(g_vq + bh * Ss * DKk);

    for (int kh = 0; kh < 2; kh++) {
        #pragma unroll
        for (int t = 0; t < 8; t++) {
            int idx = t * 256 + tid;
            int i = idx >> 4;
            int jq = (idx & 15) * 4;
            int jg = kh * 64 + jq;
            float4 pv = *(const float4*)&P[i * Ss + jg];
            half h0 = __float2half_rn(fminf(fmaxf(rintf(pv.x / ssp[jg + 0]), -128.f), 127.f));
            half h1 = __float2half_rn(fminf(fmaxf(rintf(pv.y / ssp[jg + 1]), -128.f), 127.f));
            half h2 = __float2half_rn(fminf(fmaxf(rintf(pv.z / ssp[jg + 2]), -128.f), 127.f));
            half h3 = __float2half_rn(fminf(fmaxf(rintf(pv.w / ssp[jg + 3]), -128.f), 127.f));
            half2* dst = (half2*)&As[i * 72 + jq];
            dst[0] = __halves2half2(h0, h1);
            dst[1] = __halves2half2(h2, h3);
        }
        #pragma unroll
        for (int t = 0; t < 4; t++) {
            int idx = t * 256 + tid;
            int j = idx >> 4;
            int dk4 = (idx & 15) * 4;
            int jg = kh * 64 + j;
            char4 vv = V[jg * 16 + (idx & 15)];
            float c = scc[jg];
            float f0 = c * (float)vv.x, f1 = c * (float)vv.y;
            float f2 = c * (float)vv.z, f3 = c * (float)vv.w;
            half b0 = __float2half_rn(f0), b1 = __float2half_rn(f1);
            half b2 = __float2half_rn(f2), b3 = __float2half_rn(f3);
            half l0 = __float2half_rn(f0 - __half2float(b0));
            half l1 = __float2half_rn(f1 - __half2float(b1));
            half l2 = __float2half_rn(f2 - __half2float(b2));
            half l3 = __float2half_rn(f3 - __half2float(b3));
            half2* dh = (half2*)&Bhh[j * 72 + dk4];
            dh[0] = __halves2half2(b0, b1); dh[1] = __halves2half2(b2, b3);
            half2* dl = (half2*)&Bll[j * 72 + dk4];
            dl[0] = __halves2half2(l0, l1); dl[1] = __halves2half2(l2, l3);
        }
        __syncthreads();

        #pragma unroll
        for (int ks = 0; ks < 4; ks++) {
            unsigned a[2][4];
            #pragma unroll
            for (int mf = 0; mf < 2; mf++) {
                int row = wm * 32 + mf * 16 + (lane & 15);
                ldsm_x4(a[mf][0], a[mf][1], a[mf][2], a[mf][3],
                        &As[row * 72 + ks * 16 + (lane >> 4) * 8]);
            }
            unsigned bh2[4][2], bl2[4][2];
            #pragma unroll
            for (int nh = 0; nh < 2; nh++) {
                int brow = ks * 16 + (lane & 15);
                int bcol = wn * 32 + nh * 16 + (lane >> 4) * 8;
                unsigned t0, t1, t2, t3;
                ldsm_x4_t(t0, t1, t2, t3, &Bhh[brow * 72 + bcol]);
                bh2[nh * 2][0] = t0; bh2[nh * 2][1] = t1;
                bh2[nh * 2 + 1][0] = t2; bh2[nh * 2 + 1][1] = t3;
                ldsm_x4_t(t0, t1, t2, t3, &Bll[brow * 72 + bcol]);
                bl2[nh * 2][0] = t0; bl2[nh * 2][1] = t1;
                bl2[nh * 2 + 1][0] = t2; bl2[nh * 2 + 1][1] = t3;
            }
            #pragma unroll
            for (int mf = 0; mf < 2; mf++) {
                #pragma unroll
                for (int nf = 0; nf < 4; nf++) {
                    mma_f16(acc[mf][nf], a[mf], bh2[nf]);
                    mma_f16(acc[mf][nf], a[mf], bl2[nf]);
                }
            }
        }
        __syncthreads();
    }

    int gid = lane >> 2, tg = lane & 3;
    float mx = -INFINITY;
    #pragma unroll
    for (int mf = 0; mf < 2; mf++) {
        #pragma unroll
        for (int nf = 0; nf < 4; nf++) {
            #pragma unroll
            for (int rh = 0; rh < 2; rh++) {
                int i = wm * 32 + mf * 16 + gid + rh * 8;
                int dk = wn * 32 + nf * 8 + tg * 2;
                float v0 = acc[mf][nf][rh * 2 + 0];
                float v1 = acc[mf][nf][rh * 2 + 1];
                mx = fmaxf(mx, fmaxf(v0, v1));
                *(float2*)&g_attn[(b_ * Ss + i) * DMm + h_ * DKk + dk] = make_float2(v0, v1);
            }
        }
    }
    mx = blockReduceMax(mx);
    if (tid == 0) atomicMax(&g_keys[3], fkey(mx));
}

extern "C" void kernel_launch(void* const* d_in, const int* in_sizes, int n_in,
                              void* d_out, int out_size) {
    const float* query = (const float*)d_in[0];
    const float* key   = (const float*)d_in[1];
    const float* value = (const float*)d_in[2];
    const int*   mask  = (const int*)d_in[3];
    const float* Wq = (const float*)d_in[4];
    const float* bq = (const float*)d_in[5];
    const float* Wk = (const float*)d_in[6];
    const float* bk = (const float*)d_in[7];
    const float* Wv = (const float*)d_in[8];
    const float* bv = (const float*)d_in[9];
    const float* Wo = (const float*)d_in[10];
    const float* bo = (const float*)d_in[11];
    float* out = (float*)d_out;

    const int NX4 = Mm * DMm / 4;
    const int NW4 = DMm * DMm / 4;
    const int GSM = 6 * GST;   // 61440 bytes dynamic smem for gemm

    cudaFuncSetAttribute(k_gemm_i8, cudaFuncAttributeMaxDynamicSharedMemorySize, GSM);

    k_init<<<1, 512>>>();

    k_redmaxA<<<dim3(1024, 3), 256>>>((const float4*)query, (const float4*)key,
                                      (const float4*)value, NX4);
    k_redmaxW<<<dim3(512, 4), 256>>>((const float4*)Wq, (const float4*)Wk,
                                     (const float4*)Wv, (const float4*)Wo, NW4);
    k_quantX3<<<dim3(1024, 3), 256>>>((const float4*)query, (const float4*)key,
                                      (const float4*)value, NX4);
    k_quantW4<<<dim3(512, 4), 256>>>((const float4*)Wq, (const float4*)Wk,
                                     (const float4*)Wv, (const float4*)Wo, NW4);

    dim3 gg(DMm / 128, Mm / 128);
    k_gemm_i8<<<gg, 256, GSM>>>(0, 0, bq, nullptr, 0, 4, 0);
    k_gemm_i8<<<gg, 256, GSM>>>(1, 1, bk, nullptr, 1, 5, 1);
    k_gemm_i8<<<gg, 256, GSM>>>(2, 2, bv, nullptr, 2, 6, 2);

    k_quantqkv<<<dim3(1024, 3), 256>>>();

    k_scores_fused<<<Bb * Hh, 256>>>(mask);
    k_attn_mma<<<Bb * Hh, 256>>>();

    k_quantXattn<<<2048, 256>>>(NX4);
    k_gemm_i8<<<gg, 256, GSM>>>(0, 3, bo, out, 3, 7, 3);
}